// round 11
// baseline (speedup 1.0000x reference)
#include <cuda_runtime.h>
#include <cstdint>

#define BB 4
#define SS 2048
#define NH 16
#define HD 64
#define DM 1024

// Scratch for Q/K/V in [B, H, S, hd] layout (device globals: allocation-free).
__device__ __align__(16) float g_q[BB * NH * SS * HD];
__device__ __align__(16) float g_k[BB * NH * SS * HD];
__device__ __align__(16) float g_v[BB * NH * SS * HD];

__device__ __forceinline__ unsigned f2tf(float x) {
    unsigned u;
    asm("cvt.rna.tf32.f32 %0, %1;" : "=r"(u) : "f"(x));
    return u;
}

__device__ __forceinline__ void mma_tf32(float* c, const unsigned* a, const unsigned* b) {
    asm volatile(
        "mma.sync.aligned.m16n8k8.row.col.f32.tf32.tf32.f32 "
        "{%0,%1,%2,%3}, {%4,%5,%6,%7}, {%8,%9}, {%0,%1,%2,%3};"
        : "+f"(c[0]), "+f"(c[1]), "+f"(c[2]), "+f"(c[3])
        : "r"(a[0]), "r"(a[1]), "r"(a[2]), "r"(a[3]), "r"(b[0]), "r"(b[1]));
}

// ---------------------------------------------------------------------------
// Kernel 1: fused QKV projection, tf32 MMA. R8 tile shape (128x64 block,
// 8 warps, 32x32 warp tiles, acc=32 regs) + double-buffered smem with split
// register staging (A then B) -> 1 sync per 32-k chunk, LDG/MMA overlap.
// ---------------------------------------------------------------------------
#define QSTR 36
#define QAW (128 * QSTR)              // A tile words
#define QBW (64 * QSTR)               // B tile words
#define QKV_SMEM_BYTES ((2 * QAW + 2 * QBW) * 4)   // 55296

__global__ __launch_bounds__(256) void qkv_kernel(
    const float* __restrict__ x,
    const float* __restrict__ Wq, const float* __restrict__ bq,
    const float* __restrict__ Wk, const float* __restrict__ bk,
    const float* __restrict__ Wv, const float* __restrict__ bv)
{
    extern __shared__ unsigned qsm[];
    unsigned* As[2] = { qsm, qsm + QAW };
    unsigned* Bs[2] = { qsm + 2 * QAW, qsm + 2 * QAW + QBW };

    const int tid = threadIdx.x;
    const int lane = tid & 31;
    const int w = tid >> 5;
    const int wm = w & 3;
    const int wn = w >> 2;
    const int mRow0 = wm * 32;
    const int nCol0 = wn * 32;
    const int t = lane & 3;
    const int g = lane >> 2;

    const int rowBase = blockIdx.y * 128;
    const int colBase = blockIdx.x * 64;
    const int mat = colBase / DM;
    const int colInMat = colBase % DM;
    const int head = colInMat / HD;

    const float* W    = (mat == 0) ? Wq : (mat == 1) ? Wk : Wv;
    const float* bias = (mat == 0) ? bq : (mat == 1) ? bk : bv;
    float*       dst  = (mat == 0) ? g_q : (mat == 1) ? g_k : g_v;

    // Loader mapping: row = idx>>3, c4 = (idx&7)*4.
    const int lrow = tid >> 3;          // 0..31 (+32j)
    const int lc4 = (tid & 7) * 4;

    float acc[2][4][4] = {};

    // Preload chunk 0.
    #pragma unroll
    for (int j = 0; j < 4; j++) {
        int row = lrow + j * 32;
        float4 a = *(const float4*)&x[(size_t)(rowBase + row) * DM + lc4];
        unsigned* p = &As[0][row * QSTR + lc4];
        p[0] = f2tf(a.x); p[1] = f2tf(a.y); p[2] = f2tf(a.z); p[3] = f2tf(a.w);
    }
    #pragma unroll
    for (int j = 0; j < 2; j++) {
        int row = lrow + j * 32;
        float4 bw = *(const float4*)&W[(size_t)(colInMat + row) * DM + lc4];
        unsigned* q = &Bs[0][row * QSTR + lc4];
        q[0] = f2tf(bw.x); q[1] = f2tf(bw.y); q[2] = f2tf(bw.z); q[3] = f2tf(bw.w);
    }
    __syncthreads();

    for (int c = 0; c < 32; c++) {
        const unsigned* Ac = As[c & 1];
        const unsigned* Bc = Bs[c & 1];
        unsigned* An = As[(c + 1) & 1];
        unsigned* Bn = Bs[(c + 1) & 1];
        const bool pf = (c < 31);
        const int kt = (c + 1) * 32;

        // Stage next A (16 regs, live through kk=0,1 only).
        float4 stg[4];
        if (pf) {
            #pragma unroll
            for (int j = 0; j < 4; j++)
                stg[j] = *(const float4*)&x[(size_t)(rowBase + lrow + j * 32) * DM + kt + lc4];
        }

        // MMAs kk = 0,1.
        #pragma unroll
        for (int kk = 0; kk < 2; kk++) {
            const int col = kk * 8 + t;
            unsigned a[2][4];
            #pragma unroll
            for (int mi = 0; mi < 2; mi++) {
                int r = mRow0 + mi * 16 + g;
                a[mi][0] = Ac[r * QSTR + col];
                a[mi][1] = Ac[(r + 8) * QSTR + col];
                a[mi][2] = Ac[r * QSTR + col + 4];
                a[mi][3] = Ac[(r + 8) * QSTR + col + 4];
            }
            #pragma unroll
            for (int ni = 0; ni < 4; ni++) {
                int n0 = nCol0 + ni * 8 + g;
                unsigned b[2];
                b[0] = Bc[n0 * QSTR + col];
                b[1] = Bc[n0 * QSTR + col + 4];
                mma_tf32(acc[0][ni], a[0], b);
                mma_tf32(acc[1][ni], a[1], b);
            }
        }

        // Retire A staging; stage next B (8 regs, live through kk=2,3 only).
        if (pf) {
            #pragma unroll
            for (int j = 0; j < 4; j++) {
                unsigned* p = &An[(lrow + j * 32) * QSTR + lc4];
                p[0] = f2tf(stg[j].x); p[1] = f2tf(stg[j].y);
                p[2] = f2tf(stg[j].z); p[3] = f2tf(stg[j].w);
            }
            #pragma unroll
            for (int j = 0; j < 2; j++)
                stg[j] = *(const float4*)&W[(size_t)(colInMat + lrow + j * 32) * DM + kt + lc4];
        }

        // MMAs kk = 2,3.
        #pragma unroll
        for (int kk = 2; kk < 4; kk++) {
            const int col = kk * 8 + t;
            unsigned a[2][4];
            #pragma unroll
            for (int mi = 0; mi < 2; mi++) {
                int r = mRow0 + mi * 16 + g;
                a[mi][0] = Ac[r * QSTR + col];
                a[mi][1] = Ac[(r + 8) * QSTR + col];
                a[mi][2] = Ac[r * QSTR + col + 4];
                a[mi][3] = Ac[(r + 8) * QSTR + col + 4];
            }
            #pragma unroll
            for (int ni = 0; ni < 4; ni++) {
                int n0 = nCol0 + ni * 8 + g;
                unsigned b[2];
                b[0] = Bc[n0 * QSTR + col];
                b[1] = Bc[n0 * QSTR + col + 4];
                mma_tf32(acc[0][ni], a[0], b);
                mma_tf32(acc[1][ni], a[1], b);
            }
        }

        // Retire B staging.
        if (pf) {
            #pragma unroll
            for (int j = 0; j < 2; j++) {
                unsigned* q = &Bn[(lrow + j * 32) * QSTR + lc4];
                q[0] = f2tf(stg[j].x); q[1] = f2tf(stg[j].y);
                q[2] = f2tf(stg[j].z); q[3] = f2tf(stg[j].w);
            }
        }
        __syncthreads();
    }

    // Epilogue: bias + scatter into [B,H,S,hd] (R8-proven).
    #pragma unroll
    for (int mi = 0; mi < 2; mi++) {
        #pragma unroll
        for (int ni = 0; ni < 4; ni++) {
            int d = nCol0 + ni * 8 + 2 * t;
            float b0 = bias[colInMat + d];
            float b1 = bias[colInMat + d + 1];
            #pragma unroll
            for (int half = 0; half < 2; half++) {
                int token = rowBase + mRow0 + mi * 16 + g + half * 8;
                int bidx = token >> 11;
                int s = token & (SS - 1);
                float2 o;
                o.x = acc[mi][ni][half * 2 + 0] + b0;
                o.y = acc[mi][ni][half * 2 + 1] + b1;
                *(float2*)&dst[(((size_t)(bidx * NH + head)) * SS + s) * HD + d] = o;
            }
        }
    }
}

// ---------------------------------------------------------------------------
// Kernel 2: attention (unchanged, proven ~450us): tf32 MMA, m=32 warp tiles,
// shuffle-free register P via k-permutation, double buffer, 1 sync/tile.
// ---------------------------------------------------------------------------
#define KSTR 68
#define VSTR 72
#define KWORDS (64 * KSTR)          // 4352
#define VWORDS (64 * VSTR)          // 4608
#define ATTN_SMEM_BYTES ((2 * KWORDS + 2 * VWORDS) * 4)   // 71680

__global__ __launch_bounds__(128, 2) void attn_kernel(
    const float* __restrict__ mask, float* __restrict__ out)
{
    extern __shared__ unsigned smem[];
    unsigned* kbuf[2] = { smem, smem + KWORDS };
    unsigned* vbuf[2] = { smem + 2 * KWORDS, smem + 2 * KWORDS + VWORDS };

    const int tid = threadIdx.x;
    const int lane = tid & 31;
    const int w = tid >> 5;
    const int qRow0 = w * 32;
    const int t = lane & 3;
    const int g = lane >> 2;

    const int bh = blockIdx.y;
    const int b = bh >> 4;
    const int h = bh & 15;
    const int qBase = blockIdx.x * 128;

    const float* qg = g_q + (size_t)bh * SS * HD;
    const float* kg = g_k + (size_t)bh * SS * HD;
    const float* vg = g_v + (size_t)bh * SS * HD;
    const float* maskrow = mask + b * SS;

    const float scale = 0.125f;

    // Hoist Q fragments: 2 m-frags x 8 k-steps.
    unsigned a_q[2][8][4];
    #pragma unroll
    for (int mi = 0; mi < 2; mi++) {
        int r0 = qBase + qRow0 + mi * 16 + g;
        int r1 = r0 + 8;
        #pragma unroll
        for (int kk = 0; kk < 8; kk++) {
            int col = kk * 8 + t;
            a_q[mi][kk][0] = f2tf(qg[(size_t)r0 * HD + col]);
            a_q[mi][kk][1] = f2tf(qg[(size_t)r1 * HD + col]);
            a_q[mi][kk][2] = f2tf(qg[(size_t)r0 * HD + col + 4]);
            a_q[mi][kk][3] = f2tf(qg[(size_t)r1 * HD + col + 4]);
        }
    }

    const int lrow = tid >> 4;            // 0..7 (+8j)
    const int lc4 = (tid & 15) * 4;       // 0..60

    float ctx[2][8][4] = {};

    // Preload tile 0 (V rows go to permuted slots).
    #pragma unroll
    for (int j = 0; j < 8; j++) {
        int row = lrow + j * 8;
        float4 kv = *(const float4*)&kg[(size_t)row * HD + lc4];
        uint4 ku;
        ku.x = f2tf(kv.x); ku.y = f2tf(kv.y); ku.z = f2tf(kv.z); ku.w = f2tf(kv.w);
        *(uint4*)&kbuf[0][row * KSTR + lc4] = ku;
        float4 vv = *(const float4*)&vg[(size_t)row * HD + lc4];
        uint4 vu;
        vu.x = f2tf(vv.x); vu.y = f2tf(vv.y); vu.z = f2tf(vv.z); vu.w = f2tf(vv.w);
        int vslot = (row & ~7) | ((row & 7) >> 1) | ((row & 1) << 2);
        *(uint4*)&vbuf[0][vslot * VSTR + lc4] = vu;
    }
    __syncthreads();

    for (int tt = 0; tt < 32; tt++) {
        const unsigned* kc = kbuf[tt & 1];
        const unsigned* vc = vbuf[tt & 1];
        unsigned* kn = kbuf[(tt + 1) & 1];
        unsigned* vn = vbuf[(tt + 1) & 1];
        const bool pf = (tt < 31);

        float4 stg[8];
        if (pf) {
            const float* kt = kg + (size_t)((tt + 1) * 64) * HD;
            #pragma unroll
            for (int j = 0; j < 8; j++)
                stg[j] = *(const float4*)&kt[(size_t)(lrow + j * 8) * HD + lc4];
        }

        // ---- HALF 0 : keys 0..31 ----
        {
            float s[2][4][4] = {};
            #pragma unroll
            for (int kk = 0; kk < 8; kk++) {
                #pragma unroll
                for (int ni = 0; ni < 4; ni++) {
                    const unsigned* kr = &kc[(ni * 8 + g) * KSTR + kk * 8 + t];
                    unsigned bf[2] = { kr[0], kr[4] };
                    mma_tf32(s[0][ni], a_q[0][kk], bf);
                    mma_tf32(s[1][ni], a_q[1][kk], bf);
                }
            }
            unsigned pa[2][4][4];
            #pragma unroll
            for (int ni = 0; ni < 4; ni++) {
                float2 m2 = *(const float2*)&maskrow[tt * 64 + ni * 8 + 2 * t];
                #pragma unroll
                for (int mi = 0; mi < 2; mi++) {
                    float p0 = fmaxf(s[mi][ni][0] * scale + m2.x, 0.0f);
                    float p1 = fmaxf(s[mi][ni][1] * scale + m2.y, 0.0f);
                    float p2 = fmaxf(s[mi][ni][2] * scale + m2.x, 0.0f);
                    float p3 = fmaxf(s[mi][ni][3] * scale + m2.y, 0.0f);
                    pa[mi][ni][0] = f2tf(p0 * p0);
                    pa[mi][ni][1] = f2tf(p2 * p2);
                    pa[mi][ni][2] = f2tf(p1 * p1);
                    pa[mi][ni][3] = f2tf(p3 * p3);
                }
            }
            #pragma unroll
            for (int kk = 0; kk < 4; kk++) {
                #pragma unroll
                for (int ti = 0; ti < 8; ti++) {
                    unsigned bf[2];
                    bf[0] = vc[(kk * 8 + t) * VSTR + ti * 8 + g];
                    bf[1] = vc[(kk * 8 + t + 4) * VSTR + ti * 8 + g];
                    mma_tf32(ctx[0][ti], pa[0][kk], bf);
                    mma_tf32(ctx[1][ti], pa[1][kk], bf);
                }
            }
        }

        if (pf) {
            #pragma unroll
            for (int j = 0; j < 8; j++) {
                uint4 ku;
                ku.x = f2tf(stg[j].x); ku.y = f2tf(stg[j].y);
                ku.z = f2tf(stg[j].z); ku.w = f2tf(stg[j].w);
                *(uint4*)&kn[(lrow + j * 8) * KSTR + lc4] = ku;
            }
            const float* vt = vg + (size_t)((tt + 1) * 64) * HD;
            #pragma unroll
            for (int j = 0; j < 8; j++)
                stg[j] = *(const float4*)&vt[(size_t)(lrow + j * 8) * HD + lc4];
        }

        // ---- HALF 1 : keys 32..63 ----
        {
            float s[2][4][4] = {};
            #pragma unroll
            for (int kk = 0; kk < 8; kk++) {
                #pragma unroll
                for (int ni = 0; ni < 4; ni++) {
                    const unsigned* kr = &kc[((ni + 4) * 8 + g) * KSTR + kk * 8 + t];
                    unsigned bf[2] = { kr[0], kr[4] };
                    mma_tf32(s[0][ni], a_q[0][kk], bf);
                    mma_tf32(s[1][ni], a_q[1][kk], bf);
                }
            }
            unsigned pa[2][4][4];
            #pragma unroll
            for (int ni = 0; ni < 4; ni++) {
                float2 m2 = *(const float2*)&maskrow[tt * 64 + 32 + ni * 8 + 2 * t];
                #pragma unroll
                for (int mi = 0; mi < 2; mi++) {
                    float p0 = fmaxf(s[mi][ni][0] * scale + m2.x, 0.0f);
                    float p1 = fmaxf(s[mi][ni][1] * scale + m2.y, 0.0f);
                    float p2 = fmaxf(s[mi][ni][2] * scale + m2.x, 0.0f);
                    float p3 = fmaxf(s[mi][ni][3] * scale + m2.y, 0.0f);
                    pa[mi][ni][0] = f2tf(p0 * p0);
                    pa[mi][ni][1] = f2tf(p2 * p2);
                    pa[mi][ni][2] = f2tf(p1 * p1);
                    pa[mi][ni][3] = f2tf(p3 * p3);
                }
            }
            #pragma unroll
            for (int kk = 0; kk < 4; kk++) {
                #pragma unroll
                for (int ti = 0; ti < 8; ti++) {
                    unsigned bf[2];
                    bf[0] = vc[((kk + 4) * 8 + t) * VSTR + ti * 8 + g];
                    bf[1] = vc[((kk + 4) * 8 + t + 4) * VSTR + ti * 8 + g];
                    mma_tf32(ctx[0][ti], pa[0][kk], bf);
                    mma_tf32(ctx[1][ti], pa[1][kk], bf);
                }
            }
        }

        if (pf) {
            #pragma unroll
            for (int j = 0; j < 8; j++) {
                uint4 vu;
                vu.x = f2tf(stg[j].x); vu.y = f2tf(stg[j].y);
                vu.z = f2tf(stg[j].z); vu.w = f2tf(stg[j].w);
                int row = lrow + j * 8;
                int vslot = (row & ~7) | ((row & 7) >> 1) | ((row & 1) << 2);
                *(uint4*)&vn[vslot * VSTR + lc4] = vu;
            }
        }
        __syncthreads();
    }

    // Write context: out[b][s][h*64 + d].
    #pragma unroll
    for (int mi = 0; mi < 2; mi++) {
        int r0 = qBase + qRow0 + mi * 16 + g;
        float* o0 = out + ((size_t)(b * SS + r0)) * DM + h * HD;
        float* o1 = o0 + (size_t)8 * DM;
        #pragma unroll
        for (int ti = 0; ti < 8; ti++) {
            int d = ti * 8 + 2 * t;
            *(float2*)&o0[d] = make_float2(ctx[mi][ti][0], ctx[mi][ti][1]);
            *(float2*)&o1[d] = make_float2(ctx[mi][ti][2], ctx[mi][ti][3]);
        }
    }
}

extern "C" void kernel_launch(void* const* d_in, const int* in_sizes, int n_in,
                              void* d_out, int out_size)
{
    const float* x    = (const float*)d_in[0];
    const float* mask = (const float*)d_in[1];
    const float* Wq   = (const float*)d_in[2];
    const float* bq   = (const float*)d_in[3];
    const float* Wk   = (const float*)d_in[4];
    const float* bk   = (const float*)d_in[5];
    const float* Wv   = (const float*)d_in[6];
    const float* bv   = (const float*)d_in[7];
    float* out = (float*)d_out;

    cudaFuncSetAttribute(qkv_kernel,
                         cudaFuncAttributeMaxDynamicSharedMemorySize,
                         QKV_SMEM_BYTES);
    cudaFuncSetAttribute(attn_kernel,
                         cudaFuncAttributeMaxDynamicSharedMemorySize,
                         ATTN_SMEM_BYTES);

    qkv_kernel<<<dim3(3 * DM / 64, (BB * SS) / 128), 256, QKV_SMEM_BYTES>>>(
        x, Wq, bq, Wk, bk, Wv, bv);

    attn_kernel<<<dim3(SS / 128, BB * NH), 128, ATTN_SMEM_BYTES>>>(mask, out);
}

// round 12
// speedup vs baseline: 1.2048x; 1.2048x over previous
#include <cuda_runtime.h>
#include <cstdint>

#define BB 4
#define SS 2048
#define NH 16
#define HD 64
#define DM 1024

// Scratch for Q/K/V in [B, H, S, hd] layout (device globals: allocation-free).
__device__ __align__(16) float g_q[BB * NH * SS * HD];
__device__ __align__(16) float g_k[BB * NH * SS * HD];
__device__ __align__(16) float g_v[BB * NH * SS * HD];

__device__ __forceinline__ unsigned f2tf(float x) {
    unsigned u;
    asm("cvt.rna.tf32.f32 %0, %1;" : "=r"(u) : "f"(x));
    return u;
}

__device__ __forceinline__ void mma_tf32(float* c, const unsigned* a, const unsigned* b) {
    asm volatile(
        "mma.sync.aligned.m16n8k8.row.col.f32.tf32.tf32.f32 "
        "{%0,%1,%2,%3}, {%4,%5,%6,%7}, {%8,%9}, {%0,%1,%2,%3};"
        : "+f"(c[0]), "+f"(c[1]), "+f"(c[2]), "+f"(c[3])
        : "r"(a[0]), "r"(a[1]), "r"(a[2]), "r"(a[3]), "r"(b[0]), "r"(b[1]));
}

// ---------------------------------------------------------------------------
// Kernel 1: fused QKV projection, tf32 MMA. R8 tile shape (128x64 block,
// 8 warps, 32x32 warp tiles, single smem buffer, 2 syncs/chunk) with ONE
// change: next-chunk LDGs are hoisted above the current chunk's MMAs so
// global-load latency overlaps tensor work. Staging = 24 transient regs.
// ---------------------------------------------------------------------------
__global__ __launch_bounds__(256) void qkv_kernel(
    const float* __restrict__ x,
    const float* __restrict__ Wq, const float* __restrict__ bq,
    const float* __restrict__ Wk, const float* __restrict__ bk,
    const float* __restrict__ Wv, const float* __restrict__ bv)
{
    __shared__ unsigned As[128 * 36];
    __shared__ unsigned Bs[64 * 36];

    const int tid = threadIdx.x;
    const int lane = tid & 31;
    const int w = tid >> 5;
    const int wm = w & 3;
    const int wn = w >> 2;
    const int mRow0 = wm * 32;
    const int nCol0 = wn * 32;
    const int t = lane & 3;
    const int g = lane >> 2;

    const int rowBase = blockIdx.y * 128;
    const int colBase = blockIdx.x * 64;
    const int mat = colBase / DM;
    const int colInMat = colBase % DM;
    const int head = colInMat / HD;

    const float* W    = (mat == 0) ? Wq : (mat == 1) ? Wk : Wv;
    const float* bias = (mat == 0) ? bq : (mat == 1) ? bk : bv;
    float*       dst  = (mat == 0) ? g_q : (mat == 1) ? g_k : g_v;

    // Loader mapping: row = idx>>3 (A: 0..127, B: 0..63), c4 = (idx&7)*4.
    const int lrow = tid >> 3;          // 0..31 (+32j)
    const int lc4 = (tid & 7) * 4;

    float acc[2][4][4] = {};

    // Preload chunk 0 directly into smem.
    #pragma unroll
    for (int j = 0; j < 4; j++) {
        int row = lrow + j * 32;
        float4 a = *(const float4*)&x[(size_t)(rowBase + row) * DM + lc4];
        unsigned* p = &As[row * 36 + lc4];
        p[0] = f2tf(a.x); p[1] = f2tf(a.y); p[2] = f2tf(a.z); p[3] = f2tf(a.w);
    }
    #pragma unroll
    for (int j = 0; j < 2; j++) {
        int row = lrow + j * 32;
        float4 bw = *(const float4*)&W[(size_t)(colInMat + row) * DM + lc4];
        unsigned* q = &Bs[row * 36 + lc4];
        q[0] = f2tf(bw.x); q[1] = f2tf(bw.y); q[2] = f2tf(bw.z); q[3] = f2tf(bw.w);
    }
    __syncthreads();

    for (int c = 0; c < 32; c++) {
        const bool pf = (c < 31);
        const int kt = (c + 1) * 32;

        // Hoisted LDGs for the NEXT chunk (latency hidden behind MMAs below).
        float4 xa[4], wb[2];
        if (pf) {
            #pragma unroll
            for (int j = 0; j < 4; j++)
                xa[j] = *(const float4*)&x[(size_t)(rowBase + lrow + j * 32) * DM + kt + lc4];
            #pragma unroll
            for (int j = 0; j < 2; j++)
                wb[j] = *(const float4*)&W[(size_t)(colInMat + lrow + j * 32) * DM + kt + lc4];
        }

        // 32 MMAs over 4 k-steps (current chunk).
        #pragma unroll
        for (int kk = 0; kk < 4; kk++) {
            const int col = kk * 8 + t;
            unsigned a[2][4];
            #pragma unroll
            for (int mi = 0; mi < 2; mi++) {
                int r = mRow0 + mi * 16 + g;
                a[mi][0] = As[r * 36 + col];
                a[mi][1] = As[(r + 8) * 36 + col];
                a[mi][2] = As[r * 36 + col + 4];
                a[mi][3] = As[(r + 8) * 36 + col + 4];
            }
            #pragma unroll
            for (int ni = 0; ni < 4; ni++) {
                int n0 = nCol0 + ni * 8 + g;
                unsigned b[2];
                b[0] = Bs[n0 * 36 + col];
                b[1] = Bs[n0 * 36 + col + 4];
                mma_tf32(acc[0][ni], a[0], b);
                mma_tf32(acc[1][ni], a[1], b);
            }
        }
        __syncthreads();   // all MMA reads of As/Bs done

        // Retire staging into smem (same buffer), then publish.
        if (pf) {
            #pragma unroll
            for (int j = 0; j < 4; j++) {
                unsigned* p = &As[(lrow + j * 32) * 36 + lc4];
                p[0] = f2tf(xa[j].x); p[1] = f2tf(xa[j].y);
                p[2] = f2tf(xa[j].z); p[3] = f2tf(xa[j].w);
            }
            #pragma unroll
            for (int j = 0; j < 2; j++) {
                unsigned* q = &Bs[(lrow + j * 32) * 36 + lc4];
                q[0] = f2tf(wb[j].x); q[1] = f2tf(wb[j].y);
                q[2] = f2tf(wb[j].z); q[3] = f2tf(wb[j].w);
            }
            __syncthreads();
        }
    }

    // Epilogue: bias + scatter into [B,H,S,hd] (R8-proven).
    #pragma unroll
    for (int mi = 0; mi < 2; mi++) {
        #pragma unroll
        for (int ni = 0; ni < 4; ni++) {
            int d = nCol0 + ni * 8 + 2 * t;
            float b0 = bias[colInMat + d];
            float b1 = bias[colInMat + d + 1];
            #pragma unroll
            for (int half = 0; half < 2; half++) {
                int token = rowBase + mRow0 + mi * 16 + g + half * 8;
                int bidx = token >> 11;
                int s = token & (SS - 1);
                float2 o;
                o.x = acc[mi][ni][half * 2 + 0] + b0;
                o.y = acc[mi][ni][half * 2 + 1] + b1;
                *(float2*)&dst[(((size_t)(bidx * NH + head)) * SS + s) * HD + d] = o;
            }
        }
    }
}

// ---------------------------------------------------------------------------
// Kernel 2: attention (exact R8 version, proven ~450us): tf32 MMA, m=32 warp
// tiles, shuffle-free register P via k-permutation, double buffer, 1 sync/tile.
// ---------------------------------------------------------------------------
#define KSTR 68
#define VSTR 72
#define KWORDS (64 * KSTR)          // 4352
#define VWORDS (64 * VSTR)          // 4608
#define ATTN_SMEM_BYTES ((2 * KWORDS + 2 * VWORDS) * 4)   // 71680

__global__ __launch_bounds__(128, 2) void attn_kernel(
    const float* __restrict__ mask, float* __restrict__ out)
{
    extern __shared__ unsigned smem[];
    unsigned* kbuf[2] = { smem, smem + KWORDS };
    unsigned* vbuf[2] = { smem + 2 * KWORDS, smem + 2 * KWORDS + VWORDS };

    const int tid = threadIdx.x;
    const int lane = tid & 31;
    const int w = tid >> 5;
    const int qRow0 = w * 32;
    const int t = lane & 3;
    const int g = lane >> 2;

    const int bh = blockIdx.y;
    const int b = bh >> 4;
    const int h = bh & 15;
    const int qBase = blockIdx.x * 128;

    const float* qg = g_q + (size_t)bh * SS * HD;
    const float* kg = g_k + (size_t)bh * SS * HD;
    const float* vg = g_v + (size_t)bh * SS * HD;
    const float* maskrow = mask + b * SS;

    const float scale = 0.125f;

    // Hoist Q fragments: 2 m-frags x 8 k-steps.
    unsigned a_q[2][8][4];
    #pragma unroll
    for (int mi = 0; mi < 2; mi++) {
        int r0 = qBase + qRow0 + mi * 16 + g;
        int r1 = r0 + 8;
        #pragma unroll
        for (int kk = 0; kk < 8; kk++) {
            int col = kk * 8 + t;
            a_q[mi][kk][0] = f2tf(qg[(size_t)r0 * HD + col]);
            a_q[mi][kk][1] = f2tf(qg[(size_t)r1 * HD + col]);
            a_q[mi][kk][2] = f2tf(qg[(size_t)r0 * HD + col + 4]);
            a_q[mi][kk][3] = f2tf(qg[(size_t)r1 * HD + col + 4]);
        }
    }

    const int lrow = tid >> 4;            // 0..7 (+8j)
    const int lc4 = (tid & 15) * 4;       // 0..60

    float ctx[2][8][4] = {};

    // Preload tile 0 (V rows go to permuted slots).
    #pragma unroll
    for (int j = 0; j < 8; j++) {
        int row = lrow + j * 8;
        float4 kv = *(const float4*)&kg[(size_t)row * HD + lc4];
        uint4 ku;
        ku.x = f2tf(kv.x); ku.y = f2tf(kv.y); ku.z = f2tf(kv.z); ku.w = f2tf(kv.w);
        *(uint4*)&kbuf[0][row * KSTR + lc4] = ku;
        float4 vv = *(const float4*)&vg[(size_t)row * HD + lc4];
        uint4 vu;
        vu.x = f2tf(vv.x); vu.y = f2tf(vv.y); vu.z = f2tf(vv.z); vu.w = f2tf(vv.w);
        int vslot = (row & ~7) | ((row & 7) >> 1) | ((row & 1) << 2);
        *(uint4*)&vbuf[0][vslot * VSTR + lc4] = vu;
    }
    __syncthreads();

    for (int tt = 0; tt < 32; tt++) {
        const unsigned* kc = kbuf[tt & 1];
        const unsigned* vc = vbuf[tt & 1];
        unsigned* kn = kbuf[(tt + 1) & 1];
        unsigned* vn = vbuf[(tt + 1) & 1];
        const bool pf = (tt < 31);

        float4 stg[8];
        if (pf) {
            const float* kt = kg + (size_t)((tt + 1) * 64) * HD;
            #pragma unroll
            for (int j = 0; j < 8; j++)
                stg[j] = *(const float4*)&kt[(size_t)(lrow + j * 8) * HD + lc4];
        }

        // ---- HALF 0 : keys 0..31 ----
        {
            float s[2][4][4] = {};
            #pragma unroll
            for (int kk = 0; kk < 8; kk++) {
                #pragma unroll
                for (int ni = 0; ni < 4; ni++) {
                    const unsigned* kr = &kc[(ni * 8 + g) * KSTR + kk * 8 + t];
                    unsigned bf[2] = { kr[0], kr[4] };
                    mma_tf32(s[0][ni], a_q[0][kk], bf);
                    mma_tf32(s[1][ni], a_q[1][kk], bf);
                }
            }
            unsigned pa[2][4][4];
            #pragma unroll
            for (int ni = 0; ni < 4; ni++) {
                float2 m2 = *(const float2*)&maskrow[tt * 64 + ni * 8 + 2 * t];
                #pragma unroll
                for (int mi = 0; mi < 2; mi++) {
                    float p0 = fmaxf(s[mi][ni][0] * scale + m2.x, 0.0f);
                    float p1 = fmaxf(s[mi][ni][1] * scale + m2.y, 0.0f);
                    float p2 = fmaxf(s[mi][ni][2] * scale + m2.x, 0.0f);
                    float p3 = fmaxf(s[mi][ni][3] * scale + m2.y, 0.0f);
                    pa[mi][ni][0] = f2tf(p0 * p0);
                    pa[mi][ni][1] = f2tf(p2 * p2);
                    pa[mi][ni][2] = f2tf(p1 * p1);
                    pa[mi][ni][3] = f2tf(p3 * p3);
                }
            }
            #pragma unroll
            for (int kk = 0; kk < 4; kk++) {
                #pragma unroll
                for (int ti = 0; ti < 8; ti++) {
                    unsigned bf[2];
                    bf[0] = vc[(kk * 8 + t) * VSTR + ti * 8 + g];
                    bf[1] = vc[(kk * 8 + t + 4) * VSTR + ti * 8 + g];
                    mma_tf32(ctx[0][ti], pa[0][kk], bf);
                    mma_tf32(ctx[1][ti], pa[1][kk], bf);
                }
            }
        }

        if (pf) {
            #pragma unroll
            for (int j = 0; j < 8; j++) {
                uint4 ku;
                ku.x = f2tf(stg[j].x); ku.y = f2tf(stg[j].y);
                ku.z = f2tf(stg[j].z); ku.w = f2tf(stg[j].w);
                *(uint4*)&kn[(lrow + j * 8) * KSTR + lc4] = ku;
            }
            const float* vt = vg + (size_t)((tt + 1) * 64) * HD;
            #pragma unroll
            for (int j = 0; j < 8; j++)
                stg[j] = *(const float4*)&vt[(size_t)(lrow + j * 8) * HD + lc4];
        }

        // ---- HALF 1 : keys 32..63 ----
        {
            float s[2][4][4] = {};
            #pragma unroll
            for (int kk = 0; kk < 8; kk++) {
                #pragma unroll
                for (int ni = 0; ni < 4; ni++) {
                    const unsigned* kr = &kc[((ni + 4) * 8 + g) * KSTR + kk * 8 + t];
                    unsigned bf[2] = { kr[0], kr[4] };
                    mma_tf32(s[0][ni], a_q[0][kk], bf);
                    mma_tf32(s[1][ni], a_q[1][kk], bf);
                }
            }
            unsigned pa[2][4][4];
            #pragma unroll
            for (int ni = 0; ni < 4; ni++) {
                float2 m2 = *(const float2*)&maskrow[tt * 64 + 32 + ni * 8 + 2 * t];
                #pragma unroll
                for (int mi = 0; mi < 2; mi++) {
                    float p0 = fmaxf(s[mi][ni][0] * scale + m2.x, 0.0f);
                    float p1 = fmaxf(s[mi][ni][1] * scale + m2.y, 0.0f);
                    float p2 = fmaxf(s[mi][ni][2] * scale + m2.x, 0.0f);
                    float p3 = fmaxf(s[mi][ni][3] * scale + m2.y, 0.0f);
                    pa[mi][ni][0] = f2tf(p0 * p0);
                    pa[mi][ni][1] = f2tf(p2 * p2);
                    pa[mi][ni][2] = f2tf(p1 * p1);
                    pa[mi][ni][3] = f2tf(p3 * p3);
                }
            }
            #pragma unroll
            for (int kk = 0; kk < 4; kk++) {
                #pragma unroll
                for (int ti = 0; ti < 8; ti++) {
                    unsigned bf[2];
                    bf[0] = vc[((kk + 4) * 8 + t) * VSTR + ti * 8 + g];
                    bf[1] = vc[((kk + 4) * 8 + t + 4) * VSTR + ti * 8 + g];
                    mma_tf32(ctx[0][ti], pa[0][kk], bf);
                    mma_tf32(ctx[1][ti], pa[1][kk], bf);
                }
            }
        }

        if (pf) {
            #pragma unroll
            for (int j = 0; j < 8; j++) {
                uint4 vu;
                vu.x = f2tf(stg[j].x); vu.y = f2tf(stg[j].y);
                vu.z = f2tf(stg[j].z); vu.w = f2tf(stg[j].w);
                int row = lrow + j * 8;
                int vslot = (row & ~7) | ((row & 7) >> 1) | ((row & 1) << 2);
                *(uint4*)&vn[vslot * VSTR + lc4] = vu;
            }
        }
        __syncthreads();
    }

    // Write context: out[b][s][h*64 + d].
    #pragma unroll
    for (int mi = 0; mi < 2; mi++) {
        int r0 = qBase + qRow0 + mi * 16 + g;
        float* o0 = out + ((size_t)(b * SS + r0)) * DM + h * HD;
        float* o1 = o0 + (size_t)8 * DM;
        #pragma unroll
        for (int ti = 0; ti < 8; ti++) {
            int d = ti * 8 + 2 * t;
            *(float2*)&o0[d] = make_float2(ctx[mi][ti][0], ctx[mi][ti][1]);
            *(float2*)&o1[d] = make_float2(ctx[mi][ti][2], ctx[mi][ti][3]);
        }
    }
}

extern "C" void kernel_launch(void* const* d_in, const int* in_sizes, int n_in,
                              void* d_out, int out_size)
{
    const float* x    = (const float*)d_in[0];
    const float* mask = (const float*)d_in[1];
    const float* Wq   = (const float*)d_in[2];
    const float* bq   = (const float*)d_in[3];
    const float* Wk   = (const float*)d_in[4];
    const float* bk   = (const float*)d_in[5];
    const float* Wv   = (const float*)d_in[6];
    const float* bv   = (const float*)d_in[7];
    float* out = (float*)d_out;

    cudaFuncSetAttribute(attn_kernel,
                         cudaFuncAttributeMaxDynamicSharedMemorySize,
                         ATTN_SMEM_BYTES);

    qkv_kernel<<<dim3(3 * DM / 64, (BB * SS) / 128), 256>>>(
        x, Wq, bq, Wk, bk, Wv, bv);

    attn_kernel<<<dim3(SS / 128, BB * NH), 128, ATTN_SMEM_BYTES>>>(mask, out);
}

// round 13
// speedup vs baseline: 1.2195x; 1.0122x over previous
#include <cuda_runtime.h>
#include <cstdint>

#define BB 4
#define SS 2048
#define NH 16
#define HD 64
#define DM 1024

// Scratch for Q/K/V in [B, H, S, hd] layout (device globals: allocation-free).
__device__ __align__(16) float g_q[BB * NH * SS * HD];
__device__ __align__(16) float g_k[BB * NH * SS * HD];
__device__ __align__(16) float g_v[BB * NH * SS * HD];

__device__ __forceinline__ unsigned f2tf(float x) {
    unsigned u;
    asm("cvt.rna.tf32.f32 %0, %1;" : "=r"(u) : "f"(x));
    return u;
}

__device__ __forceinline__ void mma_tf32(float* c, const unsigned* a, const unsigned* b) {
    asm volatile(
        "mma.sync.aligned.m16n8k8.row.col.f32.tf32.tf32.f32 "
        "{%0,%1,%2,%3}, {%4,%5,%6,%7}, {%8,%9}, {%0,%1,%2,%3};"
        : "+f"(c[0]), "+f"(c[1]), "+f"(c[2]), "+f"(c[3])
        : "r"(a[0]), "r"(a[1]), "r"(a[2]), "r"(a[3]), "r"(b[0]), "r"(b[1]));
}

// ---------------------------------------------------------------------------
// Kernel 1: fused QKV projection with tf32 mma.sync (EXACT R8 version, 419us).
// ---------------------------------------------------------------------------
__global__ __launch_bounds__(256) void qkv_kernel(
    const float* __restrict__ x,
    const float* __restrict__ Wq, const float* __restrict__ bq,
    const float* __restrict__ Wk, const float* __restrict__ bk,
    const float* __restrict__ Wv, const float* __restrict__ bv)
{
    __shared__ unsigned As[128 * 36];
    __shared__ unsigned Bs[64 * 36];

    const int tid = threadIdx.x;
    const int lane = tid & 31;
    const int w = tid >> 5;
    const int wm = w & 3;
    const int wn = w >> 2;
    const int mRow0 = wm * 32;
    const int nCol0 = wn * 32;

    const int rowBase = blockIdx.y * 128;
    const int colBase = blockIdx.x * 64;
    const int mat = colBase / DM;
    const int colInMat = colBase % DM;
    const int head = colInMat / HD;

    const float* W    = (mat == 0) ? Wq : (mat == 1) ? Wk : Wv;
    const float* bias = (mat == 0) ? bq : (mat == 1) ? bk : bv;
    float*       dst  = (mat == 0) ? g_q : (mat == 1) ? g_k : g_v;

    float acc[2][4][4] = {};

    for (int kt = 0; kt < DM; kt += 32) {
        #pragma unroll
        for (int j = 0; j < 4; j++) {
            int idx = tid + j * 256;
            int row = idx >> 3;
            int c4 = (idx & 7) * 4;
            float4 a = *(const float4*)&x[(size_t)(rowBase + row) * DM + kt + c4];
            unsigned* p = &As[row * 36 + c4];
            p[0] = f2tf(a.x); p[1] = f2tf(a.y); p[2] = f2tf(a.z); p[3] = f2tf(a.w);
        }
        #pragma unroll
        for (int j = 0; j < 2; j++) {
            int idx = tid + j * 256;
            int row = idx >> 3;
            int c4 = (idx & 7) * 4;
            float4 bvv = *(const float4*)&W[(size_t)(colInMat + row) * DM + kt + c4];
            unsigned* p = &Bs[row * 36 + c4];
            p[0] = f2tf(bvv.x); p[1] = f2tf(bvv.y); p[2] = f2tf(bvv.z); p[3] = f2tf(bvv.w);
        }
        __syncthreads();

        #pragma unroll
        for (int kk = 0; kk < 4; kk++) {
            const int col = kk * 8 + (lane & 3);
            unsigned a[2][4];
            #pragma unroll
            for (int mi = 0; mi < 2; mi++) {
                int r = mRow0 + mi * 16 + (lane >> 2);
                a[mi][0] = As[r * 36 + col];
                a[mi][1] = As[(r + 8) * 36 + col];
                a[mi][2] = As[r * 36 + col + 4];
                a[mi][3] = As[(r + 8) * 36 + col + 4];
            }
            #pragma unroll
            for (int ni = 0; ni < 4; ni++) {
                int n0 = nCol0 + ni * 8 + (lane >> 2);
                unsigned b[2];
                b[0] = Bs[n0 * 36 + col];
                b[1] = Bs[n0 * 36 + col + 4];
                mma_tf32(acc[0][ni], a[0], b);
                mma_tf32(acc[1][ni], a[1], b);
            }
        }
        __syncthreads();
    }

    #pragma unroll
    for (int mi = 0; mi < 2; mi++) {
        #pragma unroll
        for (int ni = 0; ni < 4; ni++) {
            int d = nCol0 + ni * 8 + 2 * (lane & 3);
            float b0 = bias[colInMat + d];
            float b1 = bias[colInMat + d + 1];
            #pragma unroll
            for (int half = 0; half < 2; half++) {
                int token = rowBase + mRow0 + mi * 16 + (lane >> 2) + half * 8;
                int bidx = token >> 11;
                int s = token & (SS - 1);
                float2 o;
                o.x = acc[mi][ni][half * 2 + 0] + b0;
                o.y = acc[mi][ni][half * 2 + 1] + b1;
                *(float2*)&dst[(((size_t)(bidx * NH + head)) * SS + s) * HD + d] = o;
            }
        }
    }
}

// ---------------------------------------------------------------------------
// Kernel 2: attention, tf32 MMA, m=32 warp tiles, n-group pipelined mainloop:
// for each 8-key group ni: 16 S MMAs -> convert s->pa (in-thread, k-permuted)
// -> 16 PV MMAs. Adjacent groups are independent -> conversion chains and
// LDS latency hide under neighboring groups' MMAs. s/pa live regs: 8+8.
// V rows stored at permuted slots rho(r)=(r>>1)|((r&1)<<2) within 8-row
// groups; K stride 68, V stride 72 (conflict-free). Double buffer, 1 sync.
// ---------------------------------------------------------------------------
#define KSTR 68
#define VSTR 72
#define KWORDS (64 * KSTR)          // 4352
#define VWORDS (64 * VSTR)          // 4608
#define ATTN_SMEM_BYTES ((2 * KWORDS + 2 * VWORDS) * 4)   // 71680

__global__ __launch_bounds__(128, 2) void attn_kernel(
    const float* __restrict__ mask, float* __restrict__ out)
{
    extern __shared__ unsigned smem[];
    unsigned* kbuf[2] = { smem, smem + KWORDS };
    unsigned* vbuf[2] = { smem + 2 * KWORDS, smem + 2 * KWORDS + VWORDS };

    const int tid = threadIdx.x;
    const int lane = tid & 31;
    const int w = tid >> 5;
    const int qRow0 = w * 32;
    const int t = lane & 3;
    const int g = lane >> 2;

    const int bh = blockIdx.y;
    const int b = bh >> 4;
    const int h = bh & 15;
    const int qBase = blockIdx.x * 128;

    const float* qg = g_q + (size_t)bh * SS * HD;
    const float* kg = g_k + (size_t)bh * SS * HD;
    const float* vg = g_v + (size_t)bh * SS * HD;
    const float* maskrow = mask + b * SS;

    const float scale = 0.125f;

    // Hoist Q fragments: 2 m-frags x 8 k-steps.
    unsigned a_q[2][8][4];
    #pragma unroll
    for (int mi = 0; mi < 2; mi++) {
        int r0 = qBase + qRow0 + mi * 16 + g;
        int r1 = r0 + 8;
        #pragma unroll
        for (int kk = 0; kk < 8; kk++) {
            int col = kk * 8 + t;
            a_q[mi][kk][0] = f2tf(qg[(size_t)r0 * HD + col]);
            a_q[mi][kk][1] = f2tf(qg[(size_t)r1 * HD + col]);
            a_q[mi][kk][2] = f2tf(qg[(size_t)r0 * HD + col + 4]);
            a_q[mi][kk][3] = f2tf(qg[(size_t)r1 * HD + col + 4]);
        }
    }

    const int lrow = tid >> 4;            // 0..7 (+8j)
    const int lc4 = (tid & 15) * 4;       // 0..60

    float ctx[2][8][4] = {};

    // Preload tile 0 (V rows go to permuted slots).
    #pragma unroll
    for (int j = 0; j < 8; j++) {
        int row = lrow + j * 8;
        float4 kv = *(const float4*)&kg[(size_t)row * HD + lc4];
        uint4 ku;
        ku.x = f2tf(kv.x); ku.y = f2tf(kv.y); ku.z = f2tf(kv.z); ku.w = f2tf(kv.w);
        *(uint4*)&kbuf[0][row * KSTR + lc4] = ku;
        float4 vv = *(const float4*)&vg[(size_t)row * HD + lc4];
        uint4 vu;
        vu.x = f2tf(vv.x); vu.y = f2tf(vv.y); vu.z = f2tf(vv.z); vu.w = f2tf(vv.w);
        int vslot = (row & ~7) | ((row & 7) >> 1) | ((row & 1) << 2);
        *(uint4*)&vbuf[0][vslot * VSTR + lc4] = vu;
    }
    __syncthreads();

    for (int tt = 0; tt < 32; tt++) {
        const unsigned* kc = kbuf[tt & 1];
        const unsigned* vc = vbuf[tt & 1];
        unsigned* kn = kbuf[(tt + 1) & 1];
        unsigned* vn = vbuf[(tt + 1) & 1];
        const bool pf = (tt < 31);

        // Stage next K (regs live through groups 0..3 only).
        float4 stg[8];
        if (pf) {
            const float* kt = kg + (size_t)((tt + 1) * 64) * HD;
            #pragma unroll
            for (int j = 0; j < 8; j++)
                stg[j] = *(const float4*)&kt[(size_t)(lrow + j * 8) * HD + lc4];
        }

        // ---- Key groups 0..3 : S(16 MMA) -> pa -> PV(16 MMA) each ----
        #pragma unroll
        for (int ni = 0; ni < 4; ni++) {
            float s[2][4] = {};
            #pragma unroll
            for (int kk = 0; kk < 8; kk++) {
                const unsigned* kr = &kc[(ni * 8 + g) * KSTR + kk * 8 + t];
                unsigned bf[2] = { kr[0], kr[4] };
                mma_tf32(s[0], a_q[0][kk], bf);
                mma_tf32(s[1], a_q[1][kk], bf);
            }
            float2 m2 = *(const float2*)&maskrow[tt * 64 + ni * 8 + 2 * t];
            unsigned pa[2][4];
            #pragma unroll
            for (int mi = 0; mi < 2; mi++) {
                float p0 = fmaxf(s[mi][0] * scale + m2.x, 0.0f);
                float p1 = fmaxf(s[mi][1] * scale + m2.y, 0.0f);
                float p2 = fmaxf(s[mi][2] * scale + m2.x, 0.0f);
                float p3 = fmaxf(s[mi][3] * scale + m2.y, 0.0f);
                pa[mi][0] = f2tf(p0 * p0);
                pa[mi][1] = f2tf(p2 * p2);
                pa[mi][2] = f2tf(p1 * p1);
                pa[mi][3] = f2tf(p3 * p3);
            }
            #pragma unroll
            for (int ti = 0; ti < 8; ti++) {
                unsigned bf[2];
                bf[0] = vc[(ni * 8 + t) * VSTR + ti * 8 + g];
                bf[1] = vc[(ni * 8 + t + 4) * VSTR + ti * 8 + g];
                mma_tf32(ctx[0][ti], pa[0], bf);
                mma_tf32(ctx[1][ti], pa[1], bf);
            }
        }

        // Retire K staging; stage next V (regs live through groups 4..7 only).
        if (pf) {
            #pragma unroll
            for (int j = 0; j < 8; j++) {
                uint4 ku;
                ku.x = f2tf(stg[j].x); ku.y = f2tf(stg[j].y);
                ku.z = f2tf(stg[j].z); ku.w = f2tf(stg[j].w);
                *(uint4*)&kn[(lrow + j * 8) * KSTR + lc4] = ku;
            }
            const float* vt = vg + (size_t)((tt + 1) * 64) * HD;
            #pragma unroll
            for (int j = 0; j < 8; j++)
                stg[j] = *(const float4*)&vt[(size_t)(lrow + j * 8) * HD + lc4];
        }

        // ---- Key groups 4..7 ----
        #pragma unroll
        for (int ni = 4; ni < 8; ni++) {
            float s[2][4] = {};
            #pragma unroll
            for (int kk = 0; kk < 8; kk++) {
                const unsigned* kr = &kc[(ni * 8 + g) * KSTR + kk * 8 + t];
                unsigned bf[2] = { kr[0], kr[4] };
                mma_tf32(s[0], a_q[0][kk], bf);
                mma_tf32(s[1], a_q[1][kk], bf);
            }
            float2 m2 = *(const float2*)&maskrow[tt * 64 + ni * 8 + 2 * t];
            unsigned pa[2][4];
            #pragma unroll
            for (int mi = 0; mi < 2; mi++) {
                float p0 = fmaxf(s[mi][0] * scale + m2.x, 0.0f);
                float p1 = fmaxf(s[mi][1] * scale + m2.y, 0.0f);
                float p2 = fmaxf(s[mi][2] * scale + m2.x, 0.0f);
                float p3 = fmaxf(s[mi][3] * scale + m2.y, 0.0f);
                pa[mi][0] = f2tf(p0 * p0);
                pa[mi][1] = f2tf(p2 * p2);
                pa[mi][2] = f2tf(p1 * p1);
                pa[mi][3] = f2tf(p3 * p3);
            }
            #pragma unroll
            for (int ti = 0; ti < 8; ti++) {
                unsigned bf[2];
                bf[0] = vc[(ni * 8 + t) * VSTR + ti * 8 + g];
                bf[1] = vc[(ni * 8 + t + 4) * VSTR + ti * 8 + g];
                mma_tf32(ctx[0][ti], pa[0], bf);
                mma_tf32(ctx[1][ti], pa[1], bf);
            }
        }

        // Retire V staging (permuted slots).
        if (pf) {
            #pragma unroll
            for (int j = 0; j < 8; j++) {
                uint4 vu;
                vu.x = f2tf(stg[j].x); vu.y = f2tf(stg[j].y);
                vu.z = f2tf(stg[j].z); vu.w = f2tf(stg[j].w);
                int row = lrow + j * 8;
                int vslot = (row & ~7) | ((row & 7) >> 1) | ((row & 1) << 2);
                *(uint4*)&vn[vslot * VSTR + lc4] = vu;
            }
        }
        __syncthreads();
    }

    // Write context: out[b][s][h*64 + d].
    #pragma unroll
    for (int mi = 0; mi < 2; mi++) {
        int r0 = qBase + qRow0 + mi * 16 + g;
        float* o0 = out + ((size_t)(b * SS + r0)) * DM + h * HD;
        float* o1 = o0 + (size_t)8 * DM;
        #pragma unroll
        for (int ti = 0; ti < 8; ti++) {
            int d = ti * 8 + 2 * t;
            *(float2*)&o0[d] = make_float2(ctx[mi][ti][0], ctx[mi][ti][1]);
            *(float2*)&o1[d] = make_float2(ctx[mi][ti][2], ctx[mi][ti][3]);
        }
    }
}

extern "C" void kernel_launch(void* const* d_in, const int* in_sizes, int n_in,
                              void* d_out, int out_size)
{
    const float* x    = (const float*)d_in[0];
    const float* mask = (const float*)d_in[1];
    const float* Wq   = (const float*)d_in[2];
    const float* bq   = (const float*)d_in[3];
    const float* Wk   = (const float*)d_in[4];
    const float* bk   = (const float*)d_in[5];
    const float* Wv   = (const float*)d_in[6];
    const float* bv   = (const float*)d_in[7];
    float* out = (float*)d_out;

    cudaFuncSetAttribute(attn_kernel,
                         cudaFuncAttributeMaxDynamicSharedMemorySize,
                         ATTN_SMEM_BYTES);

    qkv_kernel<<<dim3(3 * DM / 64, (BB * SS) / 128), 256>>>(
        x, Wq, bq, Wk, bk, Wv, bv);

    attn_kernel<<<dim3(SS / 128, BB * NH), 128, ATTN_SMEM_BYTES>>>(mask, out);
}

// round 14
// speedup vs baseline: 1.9376x; 1.5888x over previous
#include <cuda_runtime.h>
#include <cuda_fp16.h>
#include <cstdint>

#define BB 4
#define SS 2048
#define NH 16
#define HD 64
#define DM 1024
#define HW 32              // words (half2) per head-dim row

// fp16 scratch for Q/K/V in [B, H, S, hd/2-words] layout.
__device__ __align__(16) unsigned gw_q[BB * NH * SS * HW];
__device__ __align__(16) unsigned gw_k[BB * NH * SS * HW];
__device__ __align__(16) unsigned gw_v[BB * NH * SS * HW];

__device__ __forceinline__ unsigned f2h2(float lo, float hi) {
    unsigned u;
    asm("cvt.rn.f16x2.f32 %0, %1, %2;" : "=r"(u) : "f"(hi), "f"(lo));
    return u;
}

__device__ __forceinline__ void mma_f16(float* c, const unsigned* a, const unsigned* b) {
    asm volatile(
        "mma.sync.aligned.m16n8k16.row.col.f32.f16.f16.f32 "
        "{%0,%1,%2,%3}, {%4,%5,%6,%7}, {%8,%9}, {%0,%1,%2,%3};"
        : "+f"(c[0]), "+f"(c[1]), "+f"(c[2]), "+f"(c[3])
        : "r"(a[0]), "r"(a[1]), "r"(a[2]), "r"(a[3]), "r"(b[0]), "r"(b[1]));
}

// ---------------------------------------------------------------------------
// Kernel 1: fused QKV projection, fp16 MMA (m16n8k16), R8 structure.
// Tiles stored as half2 words: A 128x16w stride 20, B 64x16w stride 20.
// Writes fp16 scratch (one word per dim-pair).
// ---------------------------------------------------------------------------
#define AST 20

__global__ __launch_bounds__(256) void qkv_kernel(
    const float* __restrict__ x,
    const float* __restrict__ Wq, const float* __restrict__ bq,
    const float* __restrict__ Wk, const float* __restrict__ bk,
    const float* __restrict__ Wv, const float* __restrict__ bv)
{
    __shared__ unsigned As[128 * AST];
    __shared__ unsigned Bs[64 * AST];

    const int tid = threadIdx.x;
    const int lane = tid & 31;
    const int w = tid >> 5;
    const int wm = w & 3;
    const int wn = w >> 2;
    const int mRow0 = wm * 32;
    const int nCol0 = wn * 32;
    const int t = lane & 3;
    const int g = lane >> 2;

    const int rowBase = blockIdx.y * 128;
    const int colBase = blockIdx.x * 64;
    const int mat = colBase / DM;
    const int colInMat = colBase % DM;
    const int head = colInMat / HD;

    const float* W    = (mat == 0) ? Wq : (mat == 1) ? Wk : Wv;
    const float* bias = (mat == 0) ? bq : (mat == 1) ? bk : bv;
    unsigned*    dst  = (mat == 0) ? gw_q : (mat == 1) ? gw_k : gw_v;

    // Loader maps (words): A: row=idx>>2 (0..127), w4=(idx&3)*4, 2 iters.
    const int larow = tid >> 2;          // 0..63 (+64)
    const int law4 = (tid & 3) * 4;

    float acc[2][4][4] = {};

    for (int kt = 0; kt < DM; kt += 32) {
        #pragma unroll
        for (int j = 0; j < 2; j++) {
            int row = larow + j * 64;
            const float* src = &x[(size_t)(rowBase + row) * DM + kt + law4 * 2];
            float4 f0 = *(const float4*)src;
            float4 f1 = *(const float4*)(src + 4);
            uint4 u;
            u.x = f2h2(f0.x, f0.y); u.y = f2h2(f0.z, f0.w);
            u.z = f2h2(f1.x, f1.y); u.w = f2h2(f1.z, f1.w);
            *(uint4*)&As[row * AST + law4] = u;
        }
        {
            int row = larow;   // 0..63
            const float* src = &W[(size_t)(colInMat + row) * DM + kt + law4 * 2];
            float4 f0 = *(const float4*)src;
            float4 f1 = *(const float4*)(src + 4);
            uint4 u;
            u.x = f2h2(f0.x, f0.y); u.y = f2h2(f0.z, f0.w);
            u.z = f2h2(f1.x, f1.y); u.w = f2h2(f1.z, f1.w);
            *(uint4*)&Bs[row * AST + law4] = u;
        }
        __syncthreads();

        #pragma unroll
        for (int kc = 0; kc < 2; kc++) {
            const int col = kc * 8 + t;
            unsigned a[2][4];
            #pragma unroll
            for (int mi = 0; mi < 2; mi++) {
                int r = mRow0 + mi * 16 + g;
                a[mi][0] = As[r * AST + col];
                a[mi][1] = As[(r + 8) * AST + col];
                a[mi][2] = As[r * AST + col + 4];
                a[mi][3] = As[(r + 8) * AST + col + 4];
            }
            #pragma unroll
            for (int ni = 0; ni < 4; ni++) {
                int n0 = nCol0 + ni * 8 + g;
                unsigned b[2];
                b[0] = Bs[n0 * AST + col];
                b[1] = Bs[n0 * AST + col + 4];
                mma_f16(acc[0][ni], a[0], b);
                mma_f16(acc[1][ni], a[1], b);
            }
        }
        __syncthreads();
    }

    // Epilogue: bias + fp16 word store into [B,H,S,hd/2].
    #pragma unroll
    for (int mi = 0; mi < 2; mi++) {
        #pragma unroll
        for (int ni = 0; ni < 4; ni++) {
            int d = nCol0 + ni * 8 + 2 * t;
            float b0 = bias[colInMat + d];
            float b1 = bias[colInMat + d + 1];
            #pragma unroll
            for (int half = 0; half < 2; half++) {
                int token = rowBase + mRow0 + mi * 16 + g + half * 8;
                int bidx = token >> 11;
                int s = token & (SS - 1);
                unsigned word = f2h2(acc[mi][ni][half * 2 + 0] + b0,
                                     acc[mi][ni][half * 2 + 1] + b1);
                dst[(((size_t)(bidx * NH + head)) * SS + s) * HW + (d >> 1)] = word;
            }
        }
    }
}

// ---------------------------------------------------------------------------
// Kernel 2: attention, fp16 MMA (m16n8k16), m=32 warp tiles.
// K/V tiles: [key][word-dim], 64 x 32 words, stride 36 (conflict-free scalar
// reads 4g+t; STS.128 stores conflict-free per phase; ldmatrix rows 9r).
// S accumulators pack DIRECTLY into PV A-fragments via cvt.f16x2 (no shuffle,
// no permutation). V B-frags via ldmatrix.x4.trans. Double buffer, 1 sync.
// ---------------------------------------------------------------------------
#define KST 36
#define KWRD (64 * KST)          // 2304 words per tile
#define ATTN_SMEM_BYTES (4 * KWRD * 4)   // 2 K bufs + 2 V bufs = 36864

__global__ __launch_bounds__(128, 2) void attn_kernel(
    const float* __restrict__ mask, float* __restrict__ out)
{
    extern __shared__ unsigned smem[];
    unsigned* kbuf[2] = { smem, smem + KWRD };
    unsigned* vbuf[2] = { smem + 2 * KWRD, smem + 3 * KWRD };

    const int tid = threadIdx.x;
    const int lane = tid & 31;
    const int w = tid >> 5;
    const int qRow0 = w * 32;
    const int t = lane & 3;
    const int g = lane >> 2;

    const int bh = blockIdx.y;
    const int b = bh >> 4;
    const int h = bh & 15;
    const int qBase = blockIdx.x * 128;

    const unsigned* qg = gw_q + (size_t)bh * SS * HW;
    const unsigned* kg = gw_k + (size_t)bh * SS * HW;
    const unsigned* vg = gw_v + (size_t)bh * SS * HW;
    const float* maskrow = mask + b * SS;

    const float scale = 0.125f;

    // Hoist Q fragments: 2 m-frags x 4 k16-steps (words directly from scratch).
    unsigned a_q[2][4][4];
    #pragma unroll
    for (int mi = 0; mi < 2; mi++) {
        int r0 = qBase + qRow0 + mi * 16 + g;
        int r1 = r0 + 8;
        #pragma unroll
        for (int kc = 0; kc < 4; kc++) {
            int col = kc * 8 + t;
            a_q[mi][kc][0] = qg[(size_t)r0 * HW + col];
            a_q[mi][kc][1] = qg[(size_t)r1 * HW + col];
            a_q[mi][kc][2] = qg[(size_t)r0 * HW + col + 4];
            a_q[mi][kc][3] = qg[(size_t)r1 * HW + col + 4];
        }
    }

    // Loader map: idx = tid + j*128 (j 0..3): row = idx>>3 (0..63), w4=(idx&7)*4.
    const int lrow = tid >> 3;            // 0..15 (+16j)
    const int lw4 = (tid & 7) * 4;

    float ctx[2][8][4] = {};

    // Preload tile 0.
    #pragma unroll
    for (int j = 0; j < 4; j++) {
        int row = lrow + j * 16;
        *(uint4*)&kbuf[0][row * KST + lw4] = *(const uint4*)&kg[(size_t)row * HW + lw4];
        *(uint4*)&vbuf[0][row * KST + lw4] = *(const uint4*)&vg[(size_t)row * HW + lw4];
    }
    __syncthreads();

    const unsigned sbase = (unsigned)__cvta_generic_to_shared(smem);

    for (int tt = 0; tt < 32; tt++) {
        const unsigned* kc = kbuf[tt & 1];
        const unsigned* vc = vbuf[tt & 1];
        unsigned* kn = kbuf[(tt + 1) & 1];
        unsigned* vn = vbuf[(tt + 1) & 1];
        const unsigned vcbase = sbase + (unsigned)((2 + (tt & 1)) * KWRD) * 4u;
        const bool pf = (tt < 31);

        // Stage next K (uint4 x4, live through S phase only).
        uint4 stg[4];
        if (pf) {
            const unsigned* kt = kg + (size_t)((tt + 1) * 64) * HW;
            #pragma unroll
            for (int j = 0; j < 4; j++)
                stg[j] = *(const uint4*)&kt[(size_t)(lrow + j * 16) * HW + lw4];
        }

        // --- S = Q K^T : 64 MMAs (4 kc x 8 ni x 2 mi) ---
        float s[8][2][4];
        #pragma unroll
        for (int ni = 0; ni < 8; ni++)
            #pragma unroll
            for (int mi = 0; mi < 2; mi++)
                #pragma unroll
                for (int e = 0; e < 4; e++) s[ni][mi][e] = 0.0f;
        #pragma unroll
        for (int kc2 = 0; kc2 < 4; kc2++) {
            #pragma unroll
            for (int ni = 0; ni < 8; ni++) {
                const unsigned* kr = &kc[(ni * 8 + g) * KST + kc2 * 8 + t];
                unsigned bf[2] = { kr[0], kr[4] };
                mma_f16(s[ni][0], a_q[0][kc2], bf);
                mma_f16(s[ni][1], a_q[1][kc2], bf);
            }
        }

        // Retire K staging; stage next V.
        if (pf) {
            #pragma unroll
            for (int j = 0; j < 4; j++)
                *(uint4*)&kn[(lrow + j * 16) * KST + lw4] = stg[j];
            const unsigned* vt = vg + (size_t)((tt + 1) * 64) * HW;
            #pragma unroll
            for (int j = 0; j < 4; j++)
                stg[j] = *(const uint4*)&vt[(size_t)(lrow + j * 16) * HW + lw4];
        }

        // --- P = relu(S*scale + mask)^2 -> fp16 A-fragments (direct pack) ---
        unsigned pa[4][2][4];
        #pragma unroll
        for (int kp = 0; kp < 4; kp++) {
            #pragma unroll
            for (int half = 0; half < 2; half++) {   // n-group 2kp (+half)
                int ni = 2 * kp + half;
                float2 m2 = *(const float2*)&maskrow[tt * 64 + ni * 8 + 2 * t];
                #pragma unroll
                for (int mi = 0; mi < 2; mi++) {
                    float p0 = fmaxf(s[ni][mi][0] * scale + m2.x, 0.0f);
                    float p1 = fmaxf(s[ni][mi][1] * scale + m2.y, 0.0f);
                    float p2 = fmaxf(s[ni][mi][2] * scale + m2.x, 0.0f);
                    float p3 = fmaxf(s[ni][mi][3] * scale + m2.y, 0.0f);
                    pa[kp][mi][half * 2 + 0] = f2h2(p0 * p0, p1 * p1);
                    pa[kp][mi][half * 2 + 1] = f2h2(p2 * p2, p3 * p3);
                }
            }
        }

        // --- ctx += P @ V : 64 MMAs; V B-frags via ldmatrix.x4.trans ---
        {
            const int l = lane;
            const int vrow_off = (l & 7) + ((l >> 3) & 1) * 8;   // within 16-key chunk
            const int wcol_off = ((l >> 4) & 1) * 4;             // within 16-dim pair
            #pragma unroll
            for (int kp = 0; kp < 4; kp++) {
                #pragma unroll
                for (int tp = 0; tp < 4; tp++) {
                    unsigned addr = vcbase +
                        (unsigned)((kp * 16 + vrow_off) * KST + tp * 8 + wcol_off) * 4u;
                    unsigned r0, r1, r2, r3;
                    asm volatile(
                        "ldmatrix.sync.aligned.m8n8.x4.trans.shared.b16 "
                        "{%0,%1,%2,%3}, [%4];"
                        : "=r"(r0), "=r"(r1), "=r"(r2), "=r"(r3) : "r"(addr));
                    unsigned blo[2] = { r0, r1 };
                    unsigned bhi[2] = { r2, r3 };
                    mma_f16(ctx[0][tp * 2 + 0], pa[kp][0], blo);
                    mma_f16(ctx[1][tp * 2 + 0], pa[kp][1], blo);
                    mma_f16(ctx[0][tp * 2 + 1], pa[kp][0], bhi);
                    mma_f16(ctx[1][tp * 2 + 1], pa[kp][1], bhi);
                }
            }
        }

        // Retire V staging.
        if (pf) {
            #pragma unroll
            for (int j = 0; j < 4; j++)
                *(uint4*)&vn[(lrow + j * 16) * KST + lw4] = stg[j];
        }
        __syncthreads();
    }

    // Write context: out[b][s][h*64 + d], fp32.
    #pragma unroll
    for (int mi = 0; mi < 2; mi++) {
        int r0 = qBase + qRow0 + mi * 16 + g;
        float* o0 = out + ((size_t)(b * SS + r0)) * DM + h * HD;
        float* o1 = o0 + (size_t)8 * DM;
        #pragma unroll
        for (int ti = 0; ti < 8; ti++) {
            int d = ti * 8 + 2 * t;
            *(float2*)&o0[d] = make_float2(ctx[mi][ti][0], ctx[mi][ti][1]);
            *(float2*)&o1[d] = make_float2(ctx[mi][ti][2], ctx[mi][ti][3]);
        }
    }
}

extern "C" void kernel_launch(void* const* d_in, const int* in_sizes, int n_in,
                              void* d_out, int out_size)
{
    const float* x    = (const float*)d_in[0];
    const float* mask = (const float*)d_in[1];
    const float* Wq   = (const float*)d_in[2];
    const float* bq   = (const float*)d_in[3];
    const float* Wk   = (const float*)d_in[4];
    const float* bk   = (const float*)d_in[5];
    const float* Wv   = (const float*)d_in[6];
    const float* bv   = (const float*)d_in[7];
    float* out = (float*)d_out;

    cudaFuncSetAttribute(attn_kernel,
                         cudaFuncAttributeMaxDynamicSharedMemorySize,
                         ATTN_SMEM_BYTES);

    qkv_kernel<<<dim3(3 * DM / 64, (BB * SS) / 128), 256>>>(
        x, Wq, bq, Wk, bk, Wv, bv);

    attn_kernel<<<dim3(SS / 128, BB * NH), 128, ATTN_SMEM_BYTES>>>(mask, out);
}

// round 15
// speedup vs baseline: 2.0528x; 1.0595x over previous
#include <cuda_runtime.h>
#include <cuda_fp16.h>
#include <cstdint>

#define BB 4
#define SS 2048
#define NH 16
#define HD 64
#define DM 1024
#define HW 32              // words (half2) per head-dim row

// fp16 scratch for Q/K/V in [B, H, S, hd/2-words] layout.
__device__ __align__(16) unsigned gw_q[BB * NH * SS * HW];
__device__ __align__(16) unsigned gw_k[BB * NH * SS * HW];
__device__ __align__(16) unsigned gw_v[BB * NH * SS * HW];

__device__ __forceinline__ unsigned f2h2(float lo, float hi) {
    unsigned u;
    asm("cvt.rn.f16x2.f32 %0, %1, %2;" : "=r"(u) : "f"(hi), "f"(lo));
    return u;
}

__device__ __forceinline__ void mma_f16(float* c, const unsigned* a, const unsigned* b) {
    asm volatile(
        "mma.sync.aligned.m16n8k16.row.col.f32.f16.f16.f32 "
        "{%0,%1,%2,%3}, {%4,%5,%6,%7}, {%8,%9}, {%0,%1,%2,%3};"
        : "+f"(c[0]), "+f"(c[1]), "+f"(c[2]), "+f"(c[3])
        : "r"(a[0]), "r"(a[1]), "r"(a[2]), "r"(a[3]), "r"(b[0]), "r"(b[1]));
}

// ---------------------------------------------------------------------------
// Kernel 1: fused QKV projection, fp16 MMA (m16n8k16), k-chunk 64 (32 words):
// 32 MMAs per sync window, 16 chunks, 32 syncs total (was 16 MMAs / 64 syncs).
// A tile 128x32w stride 36, B tile 64x32w stride 36 (~27KB smem).
// ---------------------------------------------------------------------------
#define AST 36

__global__ __launch_bounds__(256) void qkv_kernel(
    const float* __restrict__ x,
    const float* __restrict__ Wq, const float* __restrict__ bq,
    const float* __restrict__ Wk, const float* __restrict__ bk,
    const float* __restrict__ Wv, const float* __restrict__ bv)
{
    __shared__ unsigned As[128 * AST];
    __shared__ unsigned Bs[64 * AST];

    const int tid = threadIdx.x;
    const int lane = tid & 31;
    const int w = tid >> 5;
    const int wm = w & 3;
    const int wn = w >> 2;
    const int mRow0 = wm * 32;
    const int nCol0 = wn * 32;
    const int t = lane & 3;
    const int g = lane >> 2;

    const int rowBase = blockIdx.y * 128;
    const int colBase = blockIdx.x * 64;
    const int mat = colBase / DM;
    const int colInMat = colBase % DM;
    const int head = colInMat / HD;

    const float* W    = (mat == 0) ? Wq : (mat == 1) ? Wk : Wv;
    const float* bias = (mat == 0) ? bq : (mat == 1) ? bk : bv;
    unsigned*    dst  = (mat == 0) ? gw_q : (mat == 1) ? gw_k : gw_v;

    // Loader map (words): row = idx>>3 (0..31 per iter), w4 = (idx&7)*4 (0..28).
    const int lrow = tid >> 3;
    const int lw4 = (tid & 7) * 4;

    float acc[2][4][4] = {};

    for (int kt = 0; kt < DM; kt += 64) {
        // A tile: 128 rows x 32 words.
        #pragma unroll
        for (int j = 0; j < 4; j++) {
            int row = lrow + j * 32;
            const float* src = &x[(size_t)(rowBase + row) * DM + kt + lw4 * 2];
            float4 f0 = *(const float4*)src;
            float4 f1 = *(const float4*)(src + 4);
            uint4 u;
            u.x = f2h2(f0.x, f0.y); u.y = f2h2(f0.z, f0.w);
            u.z = f2h2(f1.x, f1.y); u.w = f2h2(f1.z, f1.w);
            *(uint4*)&As[row * AST + lw4] = u;
        }
        // B tile: 64 rows x 32 words.
        #pragma unroll
        for (int j = 0; j < 2; j++) {
            int row = lrow + j * 32;
            const float* src = &W[(size_t)(colInMat + row) * DM + kt + lw4 * 2];
            float4 f0 = *(const float4*)src;
            float4 f1 = *(const float4*)(src + 4);
            uint4 u;
            u.x = f2h2(f0.x, f0.y); u.y = f2h2(f0.z, f0.w);
            u.z = f2h2(f1.x, f1.y); u.w = f2h2(f1.z, f1.w);
            *(uint4*)&Bs[row * AST + lw4] = u;
        }
        __syncthreads();

        #pragma unroll
        for (int kc = 0; kc < 4; kc++) {
            const int col = kc * 8 + t;
            unsigned a[2][4];
            #pragma unroll
            for (int mi = 0; mi < 2; mi++) {
                int r = mRow0 + mi * 16 + g;
                a[mi][0] = As[r * AST + col];
                a[mi][1] = As[(r + 8) * AST + col];
                a[mi][2] = As[r * AST + col + 4];
                a[mi][3] = As[(r + 8) * AST + col + 4];
            }
            #pragma unroll
            for (int ni = 0; ni < 4; ni++) {
                int n0 = nCol0 + ni * 8 + g;
                unsigned b[2];
                b[0] = Bs[n0 * AST + col];
                b[1] = Bs[n0 * AST + col + 4];
                mma_f16(acc[0][ni], a[0], b);
                mma_f16(acc[1][ni], a[1], b);
            }
        }
        __syncthreads();
    }

    // Epilogue: bias + fp16 word store into [B,H,S,hd/2].
    #pragma unroll
    for (int mi = 0; mi < 2; mi++) {
        #pragma unroll
        for (int ni = 0; ni < 4; ni++) {
            int d = nCol0 + ni * 8 + 2 * t;
            float b0 = bias[colInMat + d];
            float b1 = bias[colInMat + d + 1];
            #pragma unroll
            for (int half = 0; half < 2; half++) {
                int token = rowBase + mRow0 + mi * 16 + g + half * 8;
                int bidx = token >> 11;
                int s = token & (SS - 1);
                unsigned word = f2h2(acc[mi][ni][half * 2 + 0] + b0,
                                     acc[mi][ni][half * 2 + 1] + b1);
                dst[(((size_t)(bidx * NH + head)) * SS + s) * HW + (d >> 1)] = word;
            }
        }
    }
}

// ---------------------------------------------------------------------------
// Kernel 2: attention (EXACT R14 version, 207us): fp16 MMA, m=32 warp tiles,
// direct-pack P fragments, ldmatrix.x4.trans V frags, double buffer, 1 sync.
// ---------------------------------------------------------------------------
#define KST 36
#define KWRD (64 * KST)          // 2304 words per tile
#define ATTN_SMEM_BYTES (4 * KWRD * 4)   // 36864

__global__ __launch_bounds__(128, 2) void attn_kernel(
    const float* __restrict__ mask, float* __restrict__ out)
{
    extern __shared__ unsigned smem[];
    unsigned* kbuf[2] = { smem, smem + KWRD };
    unsigned* vbuf[2] = { smem + 2 * KWRD, smem + 3 * KWRD };

    const int tid = threadIdx.x;
    const int lane = tid & 31;
    const int w = tid >> 5;
    const int qRow0 = w * 32;
    const int t = lane & 3;
    const int g = lane >> 2;

    const int bh = blockIdx.y;
    const int b = bh >> 4;
    const int h = bh & 15;
    const int qBase = blockIdx.x * 128;

    const unsigned* qg = gw_q + (size_t)bh * SS * HW;
    const unsigned* kg = gw_k + (size_t)bh * SS * HW;
    const unsigned* vg = gw_v + (size_t)bh * SS * HW;
    const float* maskrow = mask + b * SS;

    const float scale = 0.125f;

    // Hoist Q fragments: 2 m-frags x 4 k16-steps.
    unsigned a_q[2][4][4];
    #pragma unroll
    for (int mi = 0; mi < 2; mi++) {
        int r0 = qBase + qRow0 + mi * 16 + g;
        int r1 = r0 + 8;
        #pragma unroll
        for (int kc = 0; kc < 4; kc++) {
            int col = kc * 8 + t;
            a_q[mi][kc][0] = qg[(size_t)r0 * HW + col];
            a_q[mi][kc][1] = qg[(size_t)r1 * HW + col];
            a_q[mi][kc][2] = qg[(size_t)r0 * HW + col + 4];
            a_q[mi][kc][3] = qg[(size_t)r1 * HW + col + 4];
        }
    }

    const int lrow = tid >> 3;            // 0..15 (+16j)
    const int lw4 = (tid & 7) * 4;

    float ctx[2][8][4] = {};

    // Preload tile 0.
    #pragma unroll
    for (int j = 0; j < 4; j++) {
        int row = lrow + j * 16;
        *(uint4*)&kbuf[0][row * KST + lw4] = *(const uint4*)&kg[(size_t)row * HW + lw4];
        *(uint4*)&vbuf[0][row * KST + lw4] = *(const uint4*)&vg[(size_t)row * HW + lw4];
    }
    __syncthreads();

    const unsigned sbase = (unsigned)__cvta_generic_to_shared(smem);

    for (int tt = 0; tt < 32; tt++) {
        const unsigned* kc = kbuf[tt & 1];
        unsigned* kn = kbuf[(tt + 1) & 1];
        unsigned* vn = vbuf[(tt + 1) & 1];
        const unsigned vcbase = sbase + (unsigned)((2 + (tt & 1)) * KWRD) * 4u;
        const bool pf = (tt < 31);

        uint4 stg[4];
        if (pf) {
            const unsigned* kt = kg + (size_t)((tt + 1) * 64) * HW;
            #pragma unroll
            for (int j = 0; j < 4; j++)
                stg[j] = *(const uint4*)&kt[(size_t)(lrow + j * 16) * HW + lw4];
        }

        // --- S = Q K^T : 64 MMAs ---
        float s[8][2][4];
        #pragma unroll
        for (int ni = 0; ni < 8; ni++)
            #pragma unroll
            for (int mi = 0; mi < 2; mi++)
                #pragma unroll
                for (int e = 0; e < 4; e++) s[ni][mi][e] = 0.0f;
        #pragma unroll
        for (int kc2 = 0; kc2 < 4; kc2++) {
            #pragma unroll
            for (int ni = 0; ni < 8; ni++) {
                const unsigned* kr = &kc[(ni * 8 + g) * KST + kc2 * 8 + t];
                unsigned bf[2] = { kr[0], kr[4] };
                mma_f16(s[ni][0], a_q[0][kc2], bf);
                mma_f16(s[ni][1], a_q[1][kc2], bf);
            }
        }

        if (pf) {
            #pragma unroll
            for (int j = 0; j < 4; j++)
                *(uint4*)&kn[(lrow + j * 16) * KST + lw4] = stg[j];
            const unsigned* vt = vg + (size_t)((tt + 1) * 64) * HW;
            #pragma unroll
            for (int j = 0; j < 4; j++)
                stg[j] = *(const uint4*)&vt[(size_t)(lrow + j * 16) * HW + lw4];
        }

        // --- P = relu(S*scale + mask)^2 -> fp16 A-fragments (direct pack) ---
        unsigned pa[4][2][4];
        #pragma unroll
        for (int kp = 0; kp < 4; kp++) {
            #pragma unroll
            for (int half = 0; half < 2; half++) {
                int ni = 2 * kp + half;
                float2 m2 = *(const float2*)&maskrow[tt * 64 + ni * 8 + 2 * t];
                #pragma unroll
                for (int mi = 0; mi < 2; mi++) {
                    float p0 = fmaxf(s[ni][mi][0] * scale + m2.x, 0.0f);
                    float p1 = fmaxf(s[ni][mi][1] * scale + m2.y, 0.0f);
                    float p2 = fmaxf(s[ni][mi][2] * scale + m2.x, 0.0f);
                    float p3 = fmaxf(s[ni][mi][3] * scale + m2.y, 0.0f);
                    pa[kp][mi][half * 2 + 0] = f2h2(p0 * p0, p1 * p1);
                    pa[kp][mi][half * 2 + 1] = f2h2(p2 * p2, p3 * p3);
                }
            }
        }

        // --- ctx += P @ V : 64 MMAs; V B-frags via ldmatrix.x4.trans ---
        {
            const int l = lane;
            const int vrow_off = (l & 7) + ((l >> 3) & 1) * 8;
            const int wcol_off = ((l >> 4) & 1) * 4;
            #pragma unroll
            for (int kp = 0; kp < 4; kp++) {
                #pragma unroll
                for (int tp = 0; tp < 4; tp++) {
                    unsigned addr = vcbase +
                        (unsigned)((kp * 16 + vrow_off) * KST + tp * 8 + wcol_off) * 4u;
                    unsigned r0, r1, r2, r3;
                    asm volatile(
                        "ldmatrix.sync.aligned.m8n8.x4.trans.shared.b16 "
                        "{%0,%1,%2,%3}, [%4];"
                        : "=r"(r0), "=r"(r1), "=r"(r2), "=r"(r3) : "r"(addr));
                    unsigned blo[2] = { r0, r1 };
                    unsigned bhi[2] = { r2, r3 };
                    mma_f16(ctx[0][tp * 2 + 0], pa[kp][0], blo);
                    mma_f16(ctx[1][tp * 2 + 0], pa[kp][1], blo);
                    mma_f16(ctx[0][tp * 2 + 1], pa[kp][0], bhi);
                    mma_f16(ctx[1][tp * 2 + 1], pa[kp][1], bhi);
                }
            }
        }

        if (pf) {
            #pragma unroll
            for (int j = 0; j < 4; j++)
                *(uint4*)&vn[(lrow + j * 16) * KST + lw4] = stg[j];
        }
        __syncthreads();
    }

    // Write context: out[b][s][h*64 + d], fp32.
    #pragma unroll
    for (int mi = 0; mi < 2; mi++) {
        int r0 = qBase + qRow0 + mi * 16 + g;
        float* o0 = out + ((size_t)(b * SS + r0)) * DM + h * HD;
        float* o1 = o0 + (size_t)8 * DM;
        #pragma unroll
        for (int ti = 0; ti < 8; ti++) {
            int d = ti * 8 + 2 * t;
            *(float2*)&o0[d] = make_float2(ctx[mi][ti][0], ctx[mi][ti][1]);
            *(float2*)&o1[d] = make_float2(ctx[mi][ti][2], ctx[mi][ti][3]);
        }
    }
}

extern "C" void kernel_launch(void* const* d_in, const int* in_sizes, int n_in,
                              void* d_out, int out_size)
{
    const float* x    = (const float*)d_in[0];
    const float* mask = (const float*)d_in[1];
    const float* Wq   = (const float*)d_in[2];
    const float* bq   = (const float*)d_in[3];
    const float* Wk   = (const float*)d_in[4];
    const float* bk   = (const float*)d_in[5];
    const float* Wv   = (const float*)d_in[6];
    const float* bv   = (const float*)d_in[7];
    float* out = (float*)d_out;

    cudaFuncSetAttribute(attn_kernel,
                         cudaFuncAttributeMaxDynamicSharedMemorySize,
                         ATTN_SMEM_BYTES);

    qkv_kernel<<<dim3(3 * DM / 64, (BB * SS) / 128), 256>>>(
        x, Wq, bq, Wk, bk, Wv, bv);

    attn_kernel<<<dim3(SS / 128, BB * NH), 128, ATTN_SMEM_BYTES>>>(mask, out);
}

// round 16
// speedup vs baseline: 2.6389x; 1.2855x over previous
#include <cuda_runtime.h>
#include <cuda_fp16.h>
#include <cstdint>

#define BB 4
#define SS 2048
#define NH 16
#define HD 64
#define DM 1024
#define HW 32              // words (half2) per head-dim row
#define XW (8192 * 512)    // x words (tokens x dm/2)
#define WW (1024 * 512)    // one W matrix in words

// fp16 scratch (device globals: allocation-free).
__device__ __align__(16) unsigned gw_q[BB * NH * SS * HW];
__device__ __align__(16) unsigned gw_k[BB * NH * SS * HW];
__device__ __align__(16) unsigned gw_v[BB * NH * SS * HW];
__device__ __align__(16) unsigned gw_x[XW];
__device__ __align__(16) unsigned gw_w[3 * WW];

__device__ __forceinline__ unsigned f2h2(float lo, float hi) {
    unsigned u;
    asm("cvt.rn.f16x2.f32 %0, %1, %2;" : "=r"(u) : "f"(hi), "f"(lo));
    return u;
}

__device__ __forceinline__ void mma_f16(float* c, const unsigned* a, const unsigned* b) {
    asm volatile(
        "mma.sync.aligned.m16n8k16.row.col.f32.f16.f16.f32 "
        "{%0,%1,%2,%3}, {%4,%5,%6,%7}, {%8,%9}, {%0,%1,%2,%3};"
        : "+f"(c[0]), "+f"(c[1]), "+f"(c[2]), "+f"(c[3])
        : "r"(a[0]), "r"(a[1]), "r"(a[2]), "r"(a[3]), "r"(b[0]), "r"(b[1]));
}

#define CP_ASYNC16(sa, ga) \
    asm volatile("cp.async.cg.shared.global [%0], [%1], 16;" :: "r"(sa), "l"(ga))
#define CP_COMMIT() asm volatile("cp.async.commit_group;")
#define CP_WAIT(n)  asm volatile("cp.async.wait_group %0;" :: "n"(n))

// ---------------------------------------------------------------------------
// Kernel 0: convert x and Wq/Wk/Wv (fp32) to fp16 words, once.
// Each thread: 8 floats -> 1 uint4 (4 half2 words).
// ---------------------------------------------------------------------------
__global__ __launch_bounds__(256) void cvt_kernel(
    const float* __restrict__ x,
    const float* __restrict__ Wq,
    const float* __restrict__ Wk,
    const float* __restrict__ Wv)
{
    size_t id = (size_t)blockIdx.x * 256 + threadIdx.x;
    const float* src;
    unsigned* dst;
    size_t off;
    if (id < XW / 4) {
        src = x; dst = gw_x; off = id;
    } else {
        size_t r = id - XW / 4;
        int m = (int)(r / (WW / 4));
        off = r % (WW / 4);
        src = (m == 0) ? Wq : (m == 1) ? Wk : Wv;
        dst = gw_w + (size_t)m * WW;
    }
    float4 f0 = ((const float4*)src)[off * 2];
    float4 f1 = ((const float4*)src)[off * 2 + 1];
    uint4 u;
    u.x = f2h2(f0.x, f0.y); u.y = f2h2(f0.z, f0.w);
    u.z = f2h2(f1.x, f1.y); u.w = f2h2(f1.z, f1.w);
    ((uint4*)dst)[off] = u;
}

// ---------------------------------------------------------------------------
// Kernel 1: fused QKV projection, fp16 MMA, cp.async 2-stage pipeline.
// 128x64 block tile, 8 warps (32x32 warp tiles), k-chunk 64 (32 words).
// Tiles double-buffered in dynamic smem (stride 36), loads via cp.async.
// ---------------------------------------------------------------------------
#define AST 36
#define QAW (128 * AST)
#define QBW (64 * AST)
#define TILEW (QAW + QBW)
#define QKV_SMEM_BYTES (2 * TILEW * 4)    // 55296

__global__ __launch_bounds__(256) void qkv_kernel(
    const float* __restrict__ bq, const float* __restrict__ bk,
    const float* __restrict__ bv)
{
    extern __shared__ unsigned qsm[];

    const int tid = threadIdx.x;
    const int lane = tid & 31;
    const int w = tid >> 5;
    const int wm = w & 3;
    const int wn = w >> 2;
    const int mRow0 = wm * 32;
    const int nCol0 = wn * 32;
    const int t = lane & 3;
    const int g = lane >> 2;

    const int rowBase = blockIdx.y * 128;
    const int colBase = blockIdx.x * 64;
    const int mat = colBase >> 10;
    const int colInMat = colBase & 1023;
    const int head = colInMat / HD;

    const unsigned* hx = gw_x;
    const unsigned* hwp = gw_w + (size_t)mat * WW;
    const float* bias = (mat == 0) ? bq : (mat == 1) ? bk : bv;
    unsigned*    dst  = (mat == 0) ? gw_q : (mat == 1) ? gw_k : gw_v;

    const unsigned sbase = (unsigned)__cvta_generic_to_shared(qsm);

    // cp.async loader: A = 1024 16B-segs (4/thread), B = 512 (2/thread).
    // seg id: row = id>>3 (A:0..127, B:0..63), seg = id&7 (words seg*4).
    auto issue_chunk = [&](int c) {
        const unsigned bb = (c & 1) ? (unsigned)TILEW : 0u;
        const int ktw = c * 32;
        #pragma unroll
        for (int j = 0; j < 4; j++) {
            int id = tid + j * 256;
            int row = id >> 3, seg = id & 7;
            unsigned sa = sbase + (bb + row * AST + seg * 4) * 4u;
            CP_ASYNC16(sa, &hx[(size_t)(rowBase + row) * 512 + ktw + seg * 4]);
        }
        #pragma unroll
        for (int j = 0; j < 2; j++) {
            int id = tid + j * 256;
            int row = id >> 3, seg = id & 7;
            unsigned sa = sbase + (bb + QAW + row * AST + seg * 4) * 4u;
            CP_ASYNC16(sa, &hwp[(size_t)(colInMat + row) * 512 + ktw + seg * 4]);
        }
        CP_COMMIT();
    };

    float acc[2][4][4] = {};

    issue_chunk(0);

    for (int c = 0; c < 16; c++) {
        if (c < 15) {
            issue_chunk(c + 1);
            CP_WAIT(1);
        } else {
            CP_WAIT(0);
        }
        __syncthreads();

        const unsigned* As = qsm + ((c & 1) ? TILEW : 0);
        const unsigned* Bs = As + QAW;

        #pragma unroll
        for (int kc = 0; kc < 4; kc++) {
            const int col = kc * 8 + t;
            unsigned a[2][4];
            #pragma unroll
            for (int mi = 0; mi < 2; mi++) {
                int r = mRow0 + mi * 16 + g;
                a[mi][0] = As[r * AST + col];
                a[mi][1] = As[(r + 8) * AST + col];
                a[mi][2] = As[r * AST + col + 4];
                a[mi][3] = As[(r + 8) * AST + col + 4];
            }
            #pragma unroll
            for (int ni = 0; ni < 4; ni++) {
                int n0 = nCol0 + ni * 8 + g;
                unsigned b[2];
                b[0] = Bs[n0 * AST + col];
                b[1] = Bs[n0 * AST + col + 4];
                mma_f16(acc[0][ni], a[0], b);
                mma_f16(acc[1][ni], a[1], b);
            }
        }
        __syncthreads();
    }

    // Epilogue: bias + fp16 word store into [B,H,S,hd/2].
    #pragma unroll
    for (int mi = 0; mi < 2; mi++) {
        #pragma unroll
        for (int ni = 0; ni < 4; ni++) {
            int d = nCol0 + ni * 8 + 2 * t;
            float b0 = bias[colInMat + d];
            float b1 = bias[colInMat + d + 1];
            #pragma unroll
            for (int half = 0; half < 2; half++) {
                int token = rowBase + mRow0 + mi * 16 + g + half * 8;
                int bidx = token >> 11;
                int s = token & (SS - 1);
                unsigned word = f2h2(acc[mi][ni][half * 2 + 0] + b0,
                                     acc[mi][ni][half * 2 + 1] + b1);
                dst[(((size_t)(bidx * NH + head)) * SS + s) * HW + (d >> 1)] = word;
            }
        }
    }
}

// ---------------------------------------------------------------------------
// Kernel 2: attention (EXACT R14/R15 version, ~205us): fp16 MMA, m=32 warp
// tiles, direct-pack P fragments, ldmatrix.x4.trans V, double buffer, 1 sync.
// ---------------------------------------------------------------------------
#define KST 36
#define KWRD (64 * KST)
#define ATTN_SMEM_BYTES (4 * KWRD * 4)   // 36864

__global__ __launch_bounds__(128, 2) void attn_kernel(
    const float* __restrict__ mask, float* __restrict__ out)
{
    extern __shared__ unsigned smem[];
    unsigned* kbuf[2] = { smem, smem + KWRD };
    unsigned* vbuf[2] = { smem + 2 * KWRD, smem + 3 * KWRD };

    const int tid = threadIdx.x;
    const int lane = tid & 31;
    const int w = tid >> 5;
    const int qRow0 = w * 32;
    const int t = lane & 3;
    const int g = lane >> 2;

    const int bh = blockIdx.y;
    const int b = bh >> 4;
    const int h = bh & 15;
    const int qBase = blockIdx.x * 128;

    const unsigned* qg = gw_q + (size_t)bh * SS * HW;
    const unsigned* kg = gw_k + (size_t)bh * SS * HW;
    const unsigned* vg = gw_v + (size_t)bh * SS * HW;
    const float* maskrow = mask + b * SS;

    const float scale = 0.125f;

    unsigned a_q[2][4][4];
    #pragma unroll
    for (int mi = 0; mi < 2; mi++) {
        int r0 = qBase + qRow0 + mi * 16 + g;
        int r1 = r0 + 8;
        #pragma unroll
        for (int kc = 0; kc < 4; kc++) {
            int col = kc * 8 + t;
            a_q[mi][kc][0] = qg[(size_t)r0 * HW + col];
            a_q[mi][kc][1] = qg[(size_t)r1 * HW + col];
            a_q[mi][kc][2] = qg[(size_t)r0 * HW + col + 4];
            a_q[mi][kc][3] = qg[(size_t)r1 * HW + col + 4];
        }
    }

    const int lrow = tid >> 3;
    const int lw4 = (tid & 7) * 4;

    float ctx[2][8][4] = {};

    #pragma unroll
    for (int j = 0; j < 4; j++) {
        int row = lrow + j * 16;
        *(uint4*)&kbuf[0][row * KST + lw4] = *(const uint4*)&kg[(size_t)row * HW + lw4];
        *(uint4*)&vbuf[0][row * KST + lw4] = *(const uint4*)&vg[(size_t)row * HW + lw4];
    }
    __syncthreads();

    const unsigned sbase = (unsigned)__cvta_generic_to_shared(smem);

    for (int tt = 0; tt < 32; tt++) {
        const unsigned* kc = kbuf[tt & 1];
        unsigned* kn = kbuf[(tt + 1) & 1];
        unsigned* vn = vbuf[(tt + 1) & 1];
        const unsigned vcbase = sbase + (unsigned)((2 + (tt & 1)) * KWRD) * 4u;
        const bool pf = (tt < 31);

        uint4 stg[4];
        if (pf) {
            const unsigned* kt = kg + (size_t)((tt + 1) * 64) * HW;
            #pragma unroll
            for (int j = 0; j < 4; j++)
                stg[j] = *(const uint4*)&kt[(size_t)(lrow + j * 16) * HW + lw4];
        }

        float s[8][2][4];
        #pragma unroll
        for (int ni = 0; ni < 8; ni++)
            #pragma unroll
            for (int mi = 0; mi < 2; mi++)
                #pragma unroll
                for (int e = 0; e < 4; e++) s[ni][mi][e] = 0.0f;
        #pragma unroll
        for (int kc2 = 0; kc2 < 4; kc2++) {
            #pragma unroll
            for (int ni = 0; ni < 8; ni++) {
                const unsigned* kr = &kc[(ni * 8 + g) * KST + kc2 * 8 + t];
                unsigned bf[2] = { kr[0], kr[4] };
                mma_f16(s[ni][0], a_q[0][kc2], bf);
                mma_f16(s[ni][1], a_q[1][kc2], bf);
            }
        }

        if (pf) {
            #pragma unroll
            for (int j = 0; j < 4; j++)
                *(uint4*)&kn[(lrow + j * 16) * KST + lw4] = stg[j];
            const unsigned* vt = vg + (size_t)((tt + 1) * 64) * HW;
            #pragma unroll
            for (int j = 0; j < 4; j++)
                stg[j] = *(const uint4*)&vt[(size_t)(lrow + j * 16) * HW + lw4];
        }

        unsigned pa[4][2][4];
        #pragma unroll
        for (int kp = 0; kp < 4; kp++) {
            #pragma unroll
            for (int half = 0; half < 2; half++) {
                int ni = 2 * kp + half;
                float2 m2 = *(const float2*)&maskrow[tt * 64 + ni * 8 + 2 * t];
                #pragma unroll
                for (int mi = 0; mi < 2; mi++) {
                    float p0 = fmaxf(s[ni][mi][0] * scale + m2.x, 0.0f);
                    float p1 = fmaxf(s[ni][mi][1] * scale + m2.y, 0.0f);
                    float p2 = fmaxf(s[ni][mi][2] * scale + m2.x, 0.0f);
                    float p3 = fmaxf(s[ni][mi][3] * scale + m2.y, 0.0f);
                    pa[kp][mi][half * 2 + 0] = f2h2(p0 * p0, p1 * p1);
                    pa[kp][mi][half * 2 + 1] = f2h2(p2 * p2, p3 * p3);
                }
            }
        }

        {
            const int l = lane;
            const int vrow_off = (l & 7) + ((l >> 3) & 1) * 8;
            const int wcol_off = ((l >> 4) & 1) * 4;
            #pragma unroll
            for (int kp = 0; kp < 4; kp++) {
                #pragma unroll
                for (int tp = 0; tp < 4; tp++) {
                    unsigned addr = vcbase +
                        (unsigned)((kp * 16 + vrow_off) * KST + tp * 8 + wcol_off) * 4u;
                    unsigned r0, r1, r2, r3;
                    asm volatile(
                        "ldmatrix.sync.aligned.m8n8.x4.trans.shared.b16 "
                        "{%0,%1,%2,%3}, [%4];"
                        : "=r"(r0), "=r"(r1), "=r"(r2), "=r"(r3) : "r"(addr));
                    unsigned blo[2] = { r0, r1 };
                    unsigned bhi[2] = { r2, r3 };
                    mma_f16(ctx[0][tp * 2 + 0], pa[kp][0], blo);
                    mma_f16(ctx[1][tp * 2 + 0], pa[kp][1], blo);
                    mma_f16(ctx[0][tp * 2 + 1], pa[kp][0], bhi);
                    mma_f16(ctx[1][tp * 2 + 1], pa[kp][1], bhi);
                }
            }
        }

        if (pf) {
            #pragma unroll
            for (int j = 0; j < 4; j++)
                *(uint4*)&vn[(lrow + j * 16) * KST + lw4] = stg[j];
        }
        __syncthreads();
    }

    #pragma unroll
    for (int mi = 0; mi < 2; mi++) {
        int r0 = qBase + qRow0 + mi * 16 + g;
        float* o0 = out + ((size_t)(b * SS + r0)) * DM + h * HD;
        float* o1 = o0 + (size_t)8 * DM;
        #pragma unroll
        for (int ti = 0; ti < 8; ti++) {
            int d = ti * 8 + 2 * t;
            *(float2*)&o0[d] = make_float2(ctx[mi][ti][0], ctx[mi][ti][1]);
            *(float2*)&o1[d] = make_float2(ctx[mi][ti][2], ctx[mi][ti][3]);
        }
    }
}

extern "C" void kernel_launch(void* const* d_in, const int* in_sizes, int n_in,
                              void* d_out, int out_size)
{
    const float* x    = (const float*)d_in[0];
    const float* mask = (const float*)d_in[1];
    const float* Wq   = (const float*)d_in[2];
    const float* bq   = (const float*)d_in[3];
    const float* Wk   = (const float*)d_in[4];
    const float* bk   = (const float*)d_in[5];
    const float* Wv   = (const float*)d_in[6];
    const float* bv   = (const float*)d_in[7];
    float* out = (float*)d_out;

    cudaFuncSetAttribute(qkv_kernel,
                         cudaFuncAttributeMaxDynamicSharedMemorySize,
                         QKV_SMEM_BYTES);
    cudaFuncSetAttribute(attn_kernel,
                         cudaFuncAttributeMaxDynamicSharedMemorySize,
                         ATTN_SMEM_BYTES);

    // Pre-pass: fp32 -> fp16 for x and W matrices.
    cvt_kernel<<<(XW / 4 + 3 * (WW / 4)) / 256, 256>>>(x, Wq, Wk, Wv);

    qkv_kernel<<<dim3(3 * DM / 64, (BB * SS) / 128), 256, QKV_SMEM_BYTES>>>(
        bq, bk, bv);

    attn_kernel<<<dim3(SS / 128, BB * NH), 128, ATTN_SMEM_BYTES>>>(mask, out);
}

// round 17
// speedup vs baseline: 2.6423x; 1.0013x over previous
#include <cuda_runtime.h>
#include <cuda_fp16.h>
#include <cstdint>

#define BB 4
#define SS 2048
#define NH 16
#define HD 64
#define DM 1024
#define HW 32              // words (half2) per head-dim row
#define XW (8192 * 512)    // x words (tokens x dm/2)
#define WW (1024 * 512)    // one W matrix in words

// fp16 scratch (device globals: allocation-free).
__device__ __align__(16) unsigned gw_q[BB * NH * SS * HW];
__device__ __align__(16) unsigned gw_k[BB * NH * SS * HW];
__device__ __align__(16) unsigned gw_v[BB * NH * SS * HW];
__device__ __align__(16) unsigned gw_x[XW];
__device__ __align__(16) unsigned gw_w[3 * WW];

__device__ __forceinline__ unsigned f2h2(float lo, float hi) {
    unsigned u;
    asm("cvt.rn.f16x2.f32 %0, %1, %2;" : "=r"(u) : "f"(hi), "f"(lo));
    return u;
}

__device__ __forceinline__ void mma_f16(float* c, const unsigned* a, const unsigned* b) {
    asm volatile(
        "mma.sync.aligned.m16n8k16.row.col.f32.f16.f16.f32 "
        "{%0,%1,%2,%3}, {%4,%5,%6,%7}, {%8,%9}, {%0,%1,%2,%3};"
        : "+f"(c[0]), "+f"(c[1]), "+f"(c[2]), "+f"(c[3])
        : "r"(a[0]), "r"(a[1]), "r"(a[2]), "r"(a[3]), "r"(b[0]), "r"(b[1]));
}

#define CP_ASYNC16(sa, ga) \
    asm volatile("cp.async.cg.shared.global [%0], [%1], 16;" :: "r"(sa), "l"(ga))
#define CP_COMMIT() asm volatile("cp.async.commit_group;")
#define CP_WAIT(n)  asm volatile("cp.async.wait_group %0;" :: "n"(n))

// ---------------------------------------------------------------------------
// Kernel 0: convert x and Wq/Wk/Wv (fp32) to fp16 words, once.
// Each thread: 8 floats -> 1 uint4 (4 half2 words).
// ---------------------------------------------------------------------------
__global__ __launch_bounds__(256) void cvt_kernel(
    const float* __restrict__ x,
    const float* __restrict__ Wq,
    const float* __restrict__ Wk,
    const float* __restrict__ Wv)
{
    size_t id = (size_t)blockIdx.x * 256 + threadIdx.x;
    const float* src;
    unsigned* dst;
    size_t off;
    if (id < XW / 4) {
        src = x; dst = gw_x; off = id;
    } else {
        size_t r = id - XW / 4;
        int m = (int)(r / (WW / 4));
        off = r % (WW / 4);
        src = (m == 0) ? Wq : (m == 1) ? Wk : Wv;
        dst = gw_w + (size_t)m * WW;
    }
    float4 f0 = ((const float4*)src)[off * 2];
    float4 f1 = ((const float4*)src)[off * 2 + 1];
    uint4 u;
    u.x = f2h2(f0.x, f0.y); u.y = f2h2(f0.z, f0.w);
    u.z = f2h2(f1.x, f1.y); u.w = f2h2(f1.z, f1.w);
    ((uint4*)dst)[off] = u;
}

// ---------------------------------------------------------------------------
// Kernel 1: fused QKV projection, fp16 MMA, cp.async 2-stage pipeline.
// 128x64 block tile, 8 warps (32x32 warp tiles), k-chunk 64 (32 words).
// Tiles double-buffered in dynamic smem (stride 36), loads via cp.async.
// ---------------------------------------------------------------------------
#define AST 36
#define QAW (128 * AST)
#define QBW (64 * AST)
#define TILEW (QAW + QBW)
#define QKV_SMEM_BYTES (2 * TILEW * 4)    // 55296

__global__ __launch_bounds__(256) void qkv_kernel(
    const float* __restrict__ bq, const float* __restrict__ bk,
    const float* __restrict__ bv)
{
    extern __shared__ unsigned qsm[];

    const int tid = threadIdx.x;
    const int lane = tid & 31;
    const int w = tid >> 5;
    const int wm = w & 3;
    const int wn = w >> 2;
    const int mRow0 = wm * 32;
    const int nCol0 = wn * 32;
    const int t = lane & 3;
    const int g = lane >> 2;

    const int rowBase = blockIdx.y * 128;
    const int colBase = blockIdx.x * 64;
    const int mat = colBase >> 10;
    const int colInMat = colBase & 1023;
    const int head = colInMat / HD;

    const unsigned* hx = gw_x;
    const unsigned* hwp = gw_w + (size_t)mat * WW;
    const float* bias = (mat == 0) ? bq : (mat == 1) ? bk : bv;
    unsigned*    dst  = (mat == 0) ? gw_q : (mat == 1) ? gw_k : gw_v;

    const unsigned sbase = (unsigned)__cvta_generic_to_shared(qsm);

    // cp.async loader: A = 1024 16B-segs (4/thread), B = 512 (2/thread).
    // seg id: row = id>>3 (A:0..127, B:0..63), seg = id&7 (words seg*4).
    auto issue_chunk = [&](int c) {
        const unsigned bb = (c & 1) ? (unsigned)TILEW : 0u;
        const int ktw = c * 32;
        #pragma unroll
        for (int j = 0; j < 4; j++) {
            int id = tid + j * 256;
            int row = id >> 3, seg = id & 7;
            unsigned sa = sbase + (bb + row * AST + seg * 4) * 4u;
            CP_ASYNC16(sa, &hx[(size_t)(rowBase + row) * 512 + ktw + seg * 4]);
        }
        #pragma unroll
        for (int j = 0; j < 2; j++) {
            int id = tid + j * 256;
            int row = id >> 3, seg = id & 7;
            unsigned sa = sbase + (bb + QAW + row * AST + seg * 4) * 4u;
            CP_ASYNC16(sa, &hwp[(size_t)(colInMat + row) * 512 + ktw + seg * 4]);
        }
        CP_COMMIT();
    };

    float acc[2][4][4] = {};

    issue_chunk(0);

    for (int c = 0; c < 16; c++) {
        if (c < 15) {
            issue_chunk(c + 1);
            CP_WAIT(1);
        } else {
            CP_WAIT(0);
        }
        __syncthreads();

        const unsigned* As = qsm + ((c & 1) ? TILEW : 0);
        const unsigned* Bs = As + QAW;

        #pragma unroll
        for (int kc = 0; kc < 4; kc++) {
            const int col = kc * 8 + t;
            unsigned a[2][4];
            #pragma unroll
            for (int mi = 0; mi < 2; mi++) {
                int r = mRow0 + mi * 16 + g;
                a[mi][0] = As[r * AST + col];
                a[mi][1] = As[(r + 8) * AST + col];
                a[mi][2] = As[r * AST + col + 4];
                a[mi][3] = As[(r + 8) * AST + col + 4];
            }
            #pragma unroll
            for (int ni = 0; ni < 4; ni++) {
                int n0 = nCol0 + ni * 8 + g;
                unsigned b[2];
                b[0] = Bs[n0 * AST + col];
                b[1] = Bs[n0 * AST + col + 4];
                mma_f16(acc[0][ni], a[0], b);
                mma_f16(acc[1][ni], a[1], b);
            }
        }
        __syncthreads();
    }

    // Epilogue: bias + fp16 word store into [B,H,S,hd/2].
    #pragma unroll
    for (int mi = 0; mi < 2; mi++) {
        #pragma unroll
        for (int ni = 0; ni < 4; ni++) {
            int d = nCol0 + ni * 8 + 2 * t;
            float b0 = bias[colInMat + d];
            float b1 = bias[colInMat + d + 1];
            #pragma unroll
            for (int half = 0; half < 2; half++) {
                int token = rowBase + mRow0 + mi * 16 + g + half * 8;
                int bidx = token >> 11;
                int s = token & (SS - 1);
                unsigned word = f2h2(acc[mi][ni][half * 2 + 0] + b0,
                                     acc[mi][ni][half * 2 + 1] + b1);
                dst[(((size_t)(bidx * NH + head)) * SS + s) * HW + (d >> 1)] = word;
            }
        }
    }
}

// ---------------------------------------------------------------------------
// Kernel 2: attention (EXACT R14/R15 version, ~205us): fp16 MMA, m=32 warp
// tiles, direct-pack P fragments, ldmatrix.x4.trans V, double buffer, 1 sync.
// ---------------------------------------------------------------------------
#define KST 36
#define KWRD (64 * KST)
#define ATTN_SMEM_BYTES (4 * KWRD * 4)   // 36864

__global__ __launch_bounds__(128, 2) void attn_kernel(
    const float* __restrict__ mask, float* __restrict__ out)
{
    extern __shared__ unsigned smem[];
    unsigned* kbuf[2] = { smem, smem + KWRD };
    unsigned* vbuf[2] = { smem + 2 * KWRD, smem + 3 * KWRD };

    const int tid = threadIdx.x;
    const int lane = tid & 31;
    const int w = tid >> 5;
    const int qRow0 = w * 32;
    const int t = lane & 3;
    const int g = lane >> 2;

    const int bh = blockIdx.y;
    const int b = bh >> 4;
    const int h = bh & 15;
    const int qBase = blockIdx.x * 128;

    const unsigned* qg = gw_q + (size_t)bh * SS * HW;
    const unsigned* kg = gw_k + (size_t)bh * SS * HW;
    const unsigned* vg = gw_v + (size_t)bh * SS * HW;
    const float* maskrow = mask + b * SS;

    const float scale = 0.125f;

    unsigned a_q[2][4][4];
    #pragma unroll
    for (int mi = 0; mi < 2; mi++) {
        int r0 = qBase + qRow0 + mi * 16 + g;
        int r1 = r0 + 8;
        #pragma unroll
        for (int kc = 0; kc < 4; kc++) {
            int col = kc * 8 + t;
            a_q[mi][kc][0] = qg[(size_t)r0 * HW + col];
            a_q[mi][kc][1] = qg[(size_t)r1 * HW + col];
            a_q[mi][kc][2] = qg[(size_t)r0 * HW + col + 4];
            a_q[mi][kc][3] = qg[(size_t)r1 * HW + col + 4];
        }
    }

    const int lrow = tid >> 3;
    const int lw4 = (tid & 7) * 4;

    float ctx[2][8][4] = {};

    #pragma unroll
    for (int j = 0; j < 4; j++) {
        int row = lrow + j * 16;
        *(uint4*)&kbuf[0][row * KST + lw4] = *(const uint4*)&kg[(size_t)row * HW + lw4];
        *(uint4*)&vbuf[0][row * KST + lw4] = *(const uint4*)&vg[(size_t)row * HW + lw4];
    }
    __syncthreads();

    const unsigned sbase = (unsigned)__cvta_generic_to_shared(smem);

    for (int tt = 0; tt < 32; tt++) {
        const unsigned* kc = kbuf[tt & 1];
        unsigned* kn = kbuf[(tt + 1) & 1];
        unsigned* vn = vbuf[(tt + 1) & 1];
        const unsigned vcbase = sbase + (unsigned)((2 + (tt & 1)) * KWRD) * 4u;
        const bool pf = (tt < 31);

        uint4 stg[4];
        if (pf) {
            const unsigned* kt = kg + (size_t)((tt + 1) * 64) * HW;
            #pragma unroll
            for (int j = 0; j < 4; j++)
                stg[j] = *(const uint4*)&kt[(size_t)(lrow + j * 16) * HW + lw4];
        }

        float s[8][2][4];
        #pragma unroll
        for (int ni = 0; ni < 8; ni++)
            #pragma unroll
            for (int mi = 0; mi < 2; mi++)
                #pragma unroll
                for (int e = 0; e < 4; e++) s[ni][mi][e] = 0.0f;
        #pragma unroll
        for (int kc2 = 0; kc2 < 4; kc2++) {
            #pragma unroll
            for (int ni = 0; ni < 8; ni++) {
                const unsigned* kr = &kc[(ni * 8 + g) * KST + kc2 * 8 + t];
                unsigned bf[2] = { kr[0], kr[4] };
                mma_f16(s[ni][0], a_q[0][kc2], bf);
                mma_f16(s[ni][1], a_q[1][kc2], bf);
            }
        }

        if (pf) {
            #pragma unroll
            for (int j = 0; j < 4; j++)
                *(uint4*)&kn[(lrow + j * 16) * KST + lw4] = stg[j];
            const unsigned* vt = vg + (size_t)((tt + 1) * 64) * HW;
            #pragma unroll
            for (int j = 0; j < 4; j++)
                stg[j] = *(const uint4*)&vt[(size_t)(lrow + j * 16) * HW + lw4];
        }

        unsigned pa[4][2][4];
        #pragma unroll
        for (int kp = 0; kp < 4; kp++) {
            #pragma unroll
            for (int half = 0; half < 2; half++) {
                int ni = 2 * kp + half;
                float2 m2 = *(const float2*)&maskrow[tt * 64 + ni * 8 + 2 * t];
                #pragma unroll
                for (int mi = 0; mi < 2; mi++) {
                    float p0 = fmaxf(s[ni][mi][0] * scale + m2.x, 0.0f);
                    float p1 = fmaxf(s[ni][mi][1] * scale + m2.y, 0.0f);
                    float p2 = fmaxf(s[ni][mi][2] * scale + m2.x, 0.0f);
                    float p3 = fmaxf(s[ni][mi][3] * scale + m2.y, 0.0f);
                    pa[kp][mi][half * 2 + 0] = f2h2(p0 * p0, p1 * p1);
                    pa[kp][mi][half * 2 + 1] = f2h2(p2 * p2, p3 * p3);
                }
            }
        }

        {
            const int l = lane;
            const int vrow_off = (l & 7) + ((l >> 3) & 1) * 8;
            const int wcol_off = ((l >> 4) & 1) * 4;
            #pragma unroll
            for (int kp = 0; kp < 4; kp++) {
                #pragma unroll
                for (int tp = 0; tp < 4; tp++) {
                    unsigned addr = vcbase +
                        (unsigned)((kp * 16 + vrow_off) * KST + tp * 8 + wcol_off) * 4u;
                    unsigned r0, r1, r2, r3;
                    asm volatile(
                        "ldmatrix.sync.aligned.m8n8.x4.trans.shared.b16 "
                        "{%0,%1,%2,%3}, [%4];"
                        : "=r"(r0), "=r"(r1), "=r"(r2), "=r"(r3) : "r"(addr));
                    unsigned blo[2] = { r0, r1 };
                    unsigned bhi[2] = { r2, r3 };
                    mma_f16(ctx[0][tp * 2 + 0], pa[kp][0], blo);
                    mma_f16(ctx[1][tp * 2 + 0], pa[kp][1], blo);
                    mma_f16(ctx[0][tp * 2 + 1], pa[kp][0], bhi);
                    mma_f16(ctx[1][tp * 2 + 1], pa[kp][1], bhi);
                }
            }
        }

        if (pf) {
            #pragma unroll
            for (int j = 0; j < 4; j++)
                *(uint4*)&vn[(lrow + j * 16) * KST + lw4] = stg[j];
        }
        __syncthreads();
    }

    #pragma unroll
    for (int mi = 0; mi < 2; mi++) {
        int r0 = qBase + qRow0 + mi * 16 + g;
        float* o0 = out + ((size_t)(b * SS + r0)) * DM + h * HD;
        float* o1 = o0 + (size_t)8 * DM;
        #pragma unroll
        for (int ti = 0; ti < 8; ti++) {
            int d = ti * 8 + 2 * t;
            *(float2*)&o0[d] = make_float2(ctx[mi][ti][0], ctx[mi][ti][1]);
            *(float2*)&o1[d] = make_float2(ctx[mi][ti][2], ctx[mi][ti][3]);
        }
    }
}

extern "C" void kernel_launch(void* const* d_in, const int* in_sizes, int n_in,
                              void* d_out, int out_size)
{
    const float* x    = (const float*)d_in[0];
    const float* mask = (const float*)d_in[1];
    const float* Wq   = (const float*)d_in[2];
    const float* bq   = (const float*)d_in[3];
    const float* Wk   = (const float*)d_in[4];
    const float* bk   = (const float*)d_in[5];
    const float* Wv   = (const float*)d_in[6];
    const float* bv   = (const float*)d_in[7];
    float* out = (float*)d_out;

    cudaFuncSetAttribute(qkv_kernel,
                         cudaFuncAttributeMaxDynamicSharedMemorySize,
                         QKV_SMEM_BYTES);
    cudaFuncSetAttribute(attn_kernel,
                         cudaFuncAttributeMaxDynamicSharedMemorySize,
                         ATTN_SMEM_BYTES);

    // Pre-pass: fp32 -> fp16 for x and W matrices.
    cvt_kernel<<<(XW / 4 + 3 * (WW / 4)) / 256, 256>>>(x, Wq, Wk, Wv);

    qkv_kernel<<<dim3(3 * DM / 64, (BB * SS) / 128), 256, QKV_SMEM_BYTES>>>(
        bq, bk, bv);

    attn_kernel<<<dim3(SS / 128, BB * NH), 128, ATTN_SMEM_BYTES>>>(mask, out);
}